// round 15
// baseline (speedup 1.0000x reference)
#include <cuda_runtime.h>
#include <cuda_bf16.h>
#include <math.h>
#include <stdint.h>

#define L_SEQ   2048
#define DMODEL  256
#define BATCH   4
#define MFEAT   256
#define NROWS   8192

// ===========================================================================
// Scratch
// ===========================================================================
static constexpr long SZB = (long)NROWS * DMODEL;   // 2,097,152
static constexpr long SZW = 65536;
static constexpr int  KCH = 64;

// f32 scratch
static constexpr long F_XQ    = 0;
static constexpr long F_XK    = F_XQ + SZB;
static constexpr long F_PART  = F_XK + SZB;                 // 32 * SZW
static constexpr long F_DEN   = F_PART + SZB;
static constexpr long F_KSUMP = F_DEN + NROWS;
static constexpr long F_KSUM  = F_KSUMP + (long)BATCH * KCH * MFEAT;
static constexpr long F_BIAS2 = F_KSUM + (long)BATCH * MFEAT;   // bvWo + bo
static constexpr long F_KMAX  = F_BIAS2 + MFEAT;
static constexpr long F_TOTAL = F_KMAX + 16;
__device__ float g_f[F_TOTAL];

// bf16 scratch
static constexpr long B_QINH = 0;
static constexpr long B_QINL = B_QINH + SZB;
static constexpr long B_KINH = B_QINL + SZB;
static constexpr long B_KINL = B_KINH + SZB;
static constexpr long B_VINH = B_KINL + SZB;
static constexpr long B_VINL = B_VINH + SZB;
static constexpr long B_QSH  = B_VINL + SZB;
static constexpr long B_QSL  = B_QSH + SZB;
static constexpr long B_KSH  = B_QSL + SZB;
static constexpr long B_KSL  = B_KSH + SZB;
static constexpr long B_QPH  = B_KSL + SZB;
static constexpr long B_QPL  = B_QPH + SZB;
static constexpr long B_KPH  = B_QPL + SZB;
static constexpr long B_KPL  = B_KPH + SZB;
static constexpr long B_WQTH = B_KPL + SZB;
static constexpr long B_WQTL = B_WQTH + SZW;
static constexpr long B_WKTH = B_WQTL + SZW;
static constexpr long B_WKTL = B_WKTH + SZW;
static constexpr long B_PRJH = B_WKTL + SZW;
static constexpr long B_PRJL = B_PRJH + SZW;
static constexpr long B_WVINH = B_PRJL + SZW;   // conv4 z=0
static constexpr long B_WVINL = B_WVINH + SZW;
static constexpr long B_WOINH = B_WVINL + SZW;  // conv4 z=1
static constexpr long B_WOINL = B_WOINH + SZW;
static constexpr long B_W2H  = B_WOINL + SZW;
static constexpr long B_W2L  = B_W2H + SZW;
static constexpr long B_KVUH = B_W2L + SZW;     // 4*SZW
static constexpr long B_KVUL = B_KVUH + 4 * SZW;
static constexpr long B_KVSWH = B_KVUL + 4 * SZW;
static constexpr long B_KVSWL = B_KVSWH + 4 * SZW;
static constexpr long B_TOTAL = B_KVSWL + 4 * SZW;
__device__ __nv_bfloat16 g_b[B_TOTAL];

// ===========================================================================
// Helpers
// ===========================================================================
__device__ __forceinline__ uint32_t smem_u32(const void* p) {
    uint32_t a;
    asm("{ .reg .u64 t; cvta.to.shared.u64 t, %1; cvt.u32.u64 %0, t; }"
        : "=r"(a) : "l"(p));
    return a;
}
__device__ __forceinline__ void cp16(uint32_t dst, const void* src) {
    asm volatile("cp.async.cg.shared.global [%0], [%1], 16;"
                 :: "r"(dst), "l"(src) : "memory");
}
#define CP_COMMIT()  asm volatile("cp.async.commit_group;" ::: "memory")
#define CP_WAIT0()   asm volatile("cp.async.wait_group 0;" ::: "memory")

__device__ __forceinline__ void ldsm_x4(uint32_t& r0, uint32_t& r1,
                                        uint32_t& r2, uint32_t& r3, uint32_t addr) {
    asm volatile("ldmatrix.sync.aligned.m8n8.x4.shared.b16 {%0,%1,%2,%3}, [%4];"
                 : "=r"(r0), "=r"(r1), "=r"(r2), "=r"(r3) : "r"(addr));
}
__device__ __forceinline__ void ldsm_x4_t(uint32_t& r0, uint32_t& r1,
                                          uint32_t& r2, uint32_t& r3, uint32_t addr) {
    asm volatile("ldmatrix.sync.aligned.m8n8.x4.trans.shared.b16 {%0,%1,%2,%3}, [%4];"
                 : "=r"(r0), "=r"(r1), "=r"(r2), "=r"(r3) : "r"(addr));
}
__device__ __forceinline__ void mma16816(float* d, const uint32_t* a, const uint32_t* b) {
    asm volatile("mma.sync.aligned.m16n8k16.row.col.f32.bf16.bf16.f32 "
                 "{%0,%1,%2,%3}, {%4,%5,%6,%7}, {%8,%9}, {%0,%1,%2,%3};"
                 : "+f"(d[0]), "+f"(d[1]), "+f"(d[2]), "+f"(d[3])
                 : "r"(a[0]), "r"(a[1]), "r"(a[2]), "r"(a[3]), "r"(b[0]), "r"(b[1]));
}
__device__ __forceinline__ unsigned ord_enc(float f) {
    unsigned u = __float_as_uint(f);
    return (u & 0x80000000u) ? ~u : (u | 0x80000000u);
}
__device__ __forceinline__ float ord_dec(unsigned u) {
    return __uint_as_float((u & 0x80000000u) ? (u & 0x7fffffffu) : ~u);
}
__device__ __forceinline__ float blockSum256(float v, float* sm8) {
    #pragma unroll
    for (int o = 16; o; o >>= 1) v += __shfl_xor_sync(0xffffffffu, v, o);
    if ((threadIdx.x & 31) == 0) sm8[threadIdx.x >> 5] = v;
    __syncthreads();
    float s = 0.f;
    #pragma unroll
    for (int i = 0; i < 8; i++) s += sm8[i];
    __syncthreads();
    return s;
}
__device__ __forceinline__ float blockMax256(float v, float* sm8) {
    #pragma unroll
    for (int o = 16; o; o >>= 1) v = fmaxf(v, __shfl_xor_sync(0xffffffffu, v, o));
    if ((threadIdx.x & 31) == 0) sm8[threadIdx.x >> 5] = v;
    __syncthreads();
    float s = sm8[0];
    #pragma unroll
    for (int i = 1; i < 8; i++) s = fmaxf(s, sm8[i]);
    __syncthreads();
    return s;
}
__device__ __forceinline__ void packHL(float v0, float v1,
                                       unsigned& hp, unsigned& lp) {
    __nv_bfloat16 h0 = __float2bfloat16(v0);
    __nv_bfloat16 h1 = __float2bfloat16(v1);
    float l0 = v0 - __bfloat162float(h0);
    float l1 = v1 - __bfloat162float(h1);
    hp = ((unsigned)__bfloat16_as_ushort(h1) << 16) | __bfloat16_as_ushort(h0);
    lp = ((unsigned)__bfloat16_as_ushort(__float2bfloat16(l1)) << 16)
       | __bfloat16_as_ushort(__float2bfloat16(l0));
}

// ===========================================================================
// NT GEMM (bf16 3-pass, verified): 256 thr, 8 warps (4Mx2N), K=256.
//   epiMode: 0 none, 2 +bias+rotary+0.25
//   domaxZ: if z == domaxZ, atomicMax raw acc into g_f[F_KMAX + m0>>11]
// Stage (stride 40960): Ah@0 Al@10240 Bh@20480 Bl@30720 (80B rows)
// ===========================================================================
__global__ __launch_bounds__(256, 2)
void mma_nt(const __nv_bfloat16* __restrict__ Ah, const __nv_bfloat16* __restrict__ Al,
            const __nv_bfloat16* __restrict__ Bh, const __nv_bfloat16* __restrict__ Bl,
            float* __restrict__ Cf, __nv_bfloat16* __restrict__ Ch,
            __nv_bfloat16* __restrict__ Cl,
            const float* __restrict__ bias0, const float* __restrict__ bias1,
            const float* __restrict__ pos,
            long sAb, long sBb, long sCb,
            int epiMode, int domaxZ)
{
    extern __shared__ __align__(16) char smemBuf[];

    const int tid  = threadIdx.x;
    const int wid  = tid >> 5;
    const int lane = tid & 31;
    const int warp_m = (wid >> 1) * 32;
    const int warp_n = (wid & 1) * 64;

    const int z = blockIdx.z;
    const float* bias = (z == 0) ? bias0 : bias1;
    if (Cf) Cf += (long)z * sCb;
    if (Ch) { Ch += (long)z * sCb; Cl += (long)z * sCb; }

    const int m0 = blockIdx.y * 128;
    const int n0 = blockIdx.x * 128;
    const uint32_t sbase = smem_u32(smemBuf);

    const int lrow = tid >> 1;
    const int lcol = (tid & 1) * 16;
    const long zA = (long)z * sAb;
    const long zB = (long)z * sBb;
    const __nv_bfloat16* aH = Ah + zA + (long)(m0 + lrow) * 256 + lcol;
    const __nv_bfloat16* aL = Al + zA + (long)(m0 + lrow) * 256 + lcol;
    const __nv_bfloat16* bH = Bh + zB + (long)(n0 + lrow) * 256 + lcol;
    const __nv_bfloat16* bL = Bl + zB + (long)(n0 + lrow) * 256 + lcol;
    const uint32_t dstA = sbase + lrow * 80 + (tid & 1) * 32;
    const uint32_t dstB = dstA + 20480;

    auto ldchunk = [&](int ck, int slot) {
        const int kk = ck * 32;
        const uint32_t so = slot * 40960;
        cp16(dstA + so,              aH + kk);
        cp16(dstA + so + 16,         aH + kk + 8);
        cp16(dstA + so + 10240,      aL + kk);
        cp16(dstA + so + 10240 + 16, aL + kk + 8);
        cp16(dstB + so,              bH + kk);
        cp16(dstB + so + 16,         bH + kk + 8);
        cp16(dstB + so + 10240,      bL + kk);
        cp16(dstB + so + 10240 + 16, bL + kk + 8);
    };

    const uint32_t aoffl = (warp_m + (lane & 15)) * 80 + (lane >> 4) * 16;
    const uint32_t boffl = (warp_n + (lane & 7) + ((lane >> 4) & 1) * 8) * 80
                         + ((lane >> 3) & 1) * 16;

    float acc[2][8][4] = {};

    auto compute = [&](int slot) {
        const uint32_t base = sbase + slot * 40960;
        #pragma unroll
        for (int pass = 0; pass < 3; pass++) {
            const uint32_t bA = base + ((pass == 2) ? 10240u : 0u);
            const uint32_t bB = base + 20480u + ((pass == 1) ? 10240u : 0u);
            #pragma unroll
            for (int k16 = 0; k16 < 2; k16++) {
                uint32_t a[2][4];
                #pragma unroll
                for (int mt = 0; mt < 2; mt++)
                    ldsm_x4(a[mt][0], a[mt][1], a[mt][2], a[mt][3],
                            bA + aoffl + mt * 16 * 80 + k16 * 32);
                uint32_t b[4][4];
                #pragma unroll
                for (int nt2 = 0; nt2 < 4; nt2++)
                    ldsm_x4(b[nt2][0], b[nt2][1], b[nt2][2], b[nt2][3],
                            bB + boffl + nt2 * 16 * 80 + k16 * 32);
                #pragma unroll
                for (int mt = 0; mt < 2; mt++)
                    #pragma unroll
                    for (int nt = 0; nt < 8; nt++)
                        mma16816(acc[mt][nt], a[mt], &b[nt >> 1][(nt & 1) * 2]);
            }
        }
    };

    ldchunk(0, 0); CP_COMMIT();
    #pragma unroll 1
    for (int it = 0; it < 8; it++) {
        CP_WAIT0();
        __syncthreads();
        if (it + 1 < 8) { ldchunk(it + 1, (it + 1) & 1); CP_COMMIT(); }
        compute(it & 1);
    }

    if (z == domaxZ) {
        float mx = -3.402823466e38f;
        #pragma unroll
        for (int mt = 0; mt < 2; mt++)
            #pragma unroll
            for (int nt = 0; nt < 8; nt++)
                #pragma unroll
                for (int q = 0; q < 4; q++)
                    mx = fmaxf(mx, acc[mt][nt][q]);
        __syncthreads();
        mx = blockMax256(mx, (float*)smemBuf);
        if (tid == 0)
            atomicMax((unsigned*)(g_f + F_KMAX) + (m0 >> 11), ord_enc(mx));
    }

    #pragma unroll
    for (int mt = 0; mt < 2; mt++) {
        #pragma unroll
        for (int hf = 0; hf < 2; hf++) {
            const int m = m0 + warp_m + mt * 16 + (lane >> 2) + hf * 8;
            const int l = m & (L_SEQ - 1);
            #pragma unroll
            for (int nt = 0; nt < 8; nt++) {
                const int n = n0 + warp_n + nt * 8 + (lane & 3) * 2;
                float v0 = acc[mt][nt][hf * 2 + 0];
                float v1 = acc[mt][nt][hf * 2 + 1];
                if (epiMode == 2) {
                    v0 += bias[n]; v1 += bias[n + 1];
                    const float sn = pos[(long)l * DMODEL + n];
                    const float cs = pos[(long)l * DMODEL + n + 1];
                    const float q0 = v0 * cs - v1 * sn;
                    const float q1 = v1 * cs + v0 * sn;
                    v0 = q0 * 0.25f; v1 = q1 * 0.25f;
                }
                if (Cf)
                    *(float2*)&Cf[(long)m * 256 + n] = make_float2(v0, v1);
                if (Ch) {
                    unsigned hp, lp;
                    packHL(v0, v1, hp, lp);
                    *(unsigned*)&Ch[(long)m * 256 + n] = hp;
                    *(unsigned*)&Cl[(long)m * 256 + n] = lp;
                }
            }
        }
    }
}

// ===========================================================================
// TN GEMM (bf16 3-pass, verified): A [K,M], B [K,N], ldmatrix .trans.
//   Split-K: z = bz*8+sp, 256 K-rows/split; f32 out.
// Stage (stride 34816): Ah@0 Al@8704 Bh@17408 Bl@26112 (272B rows)
// ===========================================================================
__global__ __launch_bounds__(256, 2)
void mma_tn(const __nv_bfloat16* __restrict__ Ah, const __nv_bfloat16* __restrict__ Al,
            const __nv_bfloat16* __restrict__ Bh, const __nv_bfloat16* __restrict__ Bl,
            float* __restrict__ Cf,
            long sAb, long sAs, long sBb, long sBs, long sCb, long sCs)
{
    extern __shared__ __align__(16) char smemBuf[];

    const int tid  = threadIdx.x;
    const int wid  = tid >> 5;
    const int lane = tid & 31;
    const int warp_m = (wid >> 1) * 32;
    const int warp_n = (wid & 1) * 64;

    const int z  = blockIdx.z;
    const int bz = z >> 3, sp = z & 7;
    const long aoff = (long)bz * sAb + (long)sp * sAs;
    const long boff = (long)bz * sBb + (long)sp * sBs;
    Cf += (long)bz * sCb + (long)sp * sCs;

    const int m0 = blockIdx.y * 128;
    const int n0 = blockIdx.x * 128;
    const uint32_t sbase = smem_u32(smemBuf);

    const int lrow = tid >> 3;
    const int lcol = (tid & 7) * 16;
    const __nv_bfloat16* aH = Ah + aoff + (long)lrow * 256 + m0 + lcol;
    const __nv_bfloat16* aL = Al + aoff + (long)lrow * 256 + m0 + lcol;
    const __nv_bfloat16* bH = Bh + boff + (long)lrow * 256 + n0 + lcol;
    const __nv_bfloat16* bL = Bl + boff + (long)lrow * 256 + n0 + lcol;
    const uint32_t dstA = sbase + lrow * 272 + (tid & 7) * 32;
    const uint32_t dstB = dstA + 17408;

    auto ldchunk = [&](int ck, int slot) {
        const long kk = (long)ck * 32 * 256;
        const uint32_t so = slot * 34816;
        cp16(dstA + so,             aH + kk);
        cp16(dstA + so + 16,        aH + kk + 8);
        cp16(dstA + so + 8704,      aL + kk);
        cp16(dstA + so + 8704 + 16, aL + kk + 8);
        cp16(dstB + so,             bH + kk);
        cp16(dstB + so + 16,        bH + kk + 8);
        cp16(dstB + so + 8704,      bL + kk);
        cp16(dstB + so + 8704 + 16, bL + kk + 8);
    };

    const uint32_t aoffl = ((lane & 7) + ((lane >> 4) & 1) * 8) * 272
                         + (warp_m + ((lane >> 3) & 1) * 8) * 2;
    const uint32_t boffl = ((lane & 7) + ((lane >> 3) & 1) * 8) * 272
                         + (warp_n + ((lane >> 4) & 1) * 8) * 2;

    float acc[2][8][4] = {};

    auto compute = [&](int slot) {
        const uint32_t base = sbase + slot * 34816;
        #pragma unroll
        for (int pass = 0; pass < 3; pass++) {
            const uint32_t bA = base + ((pass == 2) ? 8704u : 0u);
            const uint32_t bB = base + 17408u + ((pass == 1) ? 8704u : 0u);
            #pragma unroll
            for (int k16 = 0; k16 < 2; k16++) {
                uint32_t a[2][4];
                #pragma unroll
                for (int mt = 0; mt < 2; mt++)
                    ldsm_x4_t(a[mt][0], a[mt][1], a[mt][2], a[mt][3],
                              bA + aoffl + k16 * 16 * 272 + mt * 16 * 2);
                uint32_t b[4][4];
                #pragma unroll
                for (int nt2 = 0; nt2 < 4; nt2++)
                    ldsm_x4_t(b[nt2][0], b[nt2][1], b[nt2][2], b[nt2][3],
                              bB + boffl + k16 * 16 * 272 + nt2 * 16 * 2);
                #pragma unroll
                for (int mt = 0; mt < 2; mt++)
                    #pragma unroll
                    for (int nt = 0; nt < 8; nt++)
                        mma16816(acc[mt][nt], a[mt], &b[nt >> 1][(nt & 1) * 2]);
            }
        }
    };

    ldchunk(0, 0); CP_COMMIT();
    #pragma unroll 1
    for (int it = 0; it < 8; it++) {
        CP_WAIT0();
        __syncthreads();
        if (it + 1 < 8) { ldchunk(it + 1, (it + 1) & 1); CP_COMMIT(); }
        compute(it & 1);
    }

    #pragma unroll
    for (int mt = 0; mt < 2; mt++)
        #pragma unroll
        for (int hf = 0; hf < 2; hf++) {
            const int m = m0 + warp_m + mt * 16 + (lane >> 2) + hf * 8;
            #pragma unroll
            for (int nt = 0; nt < 8; nt++) {
                const int n = n0 + warp_n + nt * 8 + (lane & 3) * 2;
                *(float2*)&Cf[(long)m * 256 + n] =
                    make_float2(acc[mt][nt][hf * 2], acc[mt][nt][hf * 2 + 1]);
            }
        }
}

// ===========================================================================
// NN GEMM (bf16 3-pass): A [M,K=256] row-major, B [K=256,N] row-major.
//   epi: 0 none, 5 = /den[m] + bias[n]
// Stage (stride 37888): Ah@0 Al@10240 Bh@20480 Bl@29184
// ===========================================================================
__global__ __launch_bounds__(256, 2)
void mma_nn(const __nv_bfloat16* __restrict__ Ah, const __nv_bfloat16* __restrict__ Al,
            const __nv_bfloat16* __restrict__ Bh, const __nv_bfloat16* __restrict__ Bl,
            float* __restrict__ Cf, __nv_bfloat16* __restrict__ Ch,
            __nv_bfloat16* __restrict__ Cl,
            const float* __restrict__ bias, const float* __restrict__ den,
            long sAb, long sBb, long sCb, long sDen, int epi)
{
    extern __shared__ __align__(16) char smemBuf[];   // 2 x 37888

    const int tid  = threadIdx.x;
    const int wid  = tid >> 5;
    const int lane = tid & 31;
    const int warp_m = (wid >> 1) * 32;
    const int warp_n = (wid & 1) * 64;

    const int z = blockIdx.z;
    Ah += (long)z * sAb; Al += (long)z * sAb;
    Bh += (long)z * sBb; Bl += (long)z * sBb;
    if (Cf) Cf += (long)z * sCb;
    if (Ch) { Ch += (long)z * sCb; Cl += (long)z * sCb; }
    if (epi == 5) den += (long)z * sDen;

    const int m0 = blockIdx.y * 128;
    const int n0 = blockIdx.x * 128;
    const uint32_t sbase = smem_u32(smemBuf);

    const int lrowA = tid >> 1;
    const __nv_bfloat16* aH = Ah + (long)(m0 + lrowA) * 256 + (tid & 1) * 16;
    const __nv_bfloat16* aL = Al + (long)(m0 + lrowA) * 256 + (tid & 1) * 16;
    const uint32_t dstA = sbase + lrowA * 80 + (tid & 1) * 32;
    const int lrowB = tid >> 3;
    const __nv_bfloat16* bH = Bh + (long)lrowB * 256 + n0 + (tid & 7) * 16;
    const __nv_bfloat16* bL = Bl + (long)lrowB * 256 + n0 + (tid & 7) * 16;
    const uint32_t dstB = sbase + 20480 + lrowB * 272 + (tid & 7) * 32;

    auto ldchunk = [&](int ck, int slot) {
        const int  kkA = ck * 32;
        const long kkB = (long)ck * 32 * 256;
        const uint32_t so = slot * 37888;
        cp16(dstA + so,              aH + kkA);
        cp16(dstA + so + 16,         aH + kkA + 8);
        cp16(dstA + so + 10240,      aL + kkA);
        cp16(dstA + so + 10240 + 16, aL + kkA + 8);
        cp16(dstB + so,             bH + kkB);
        cp16(dstB + so + 16,        bH + kkB + 8);
        cp16(dstB + so + 8704,      bL + kkB);
        cp16(dstB + so + 8704 + 16, bL + kkB + 8);
    };

    const uint32_t aoffl = (warp_m + (lane & 15)) * 80 + (lane >> 4) * 16;
    const uint32_t boffl = ((lane & 7) + ((lane >> 3) & 1) * 8) * 272
                         + (warp_n + ((lane >> 4) & 1) * 8) * 2;

    float acc[2][8][4] = {};

    auto compute = [&](int slot) {
        const uint32_t base = sbase + slot * 37888;
        #pragma unroll
        for (int pass = 0; pass < 3; pass++) {
            const uint32_t bA = base + ((pass == 2) ? 10240u : 0u);
            const uint32_t bB = base + 20480u + ((pass == 1) ? 8704u : 0u);
            #pragma unroll
            for (int k16 = 0; k16 < 2; k16++) {
                uint32_t a[2][4];
                #pragma unroll
                for (int mt = 0; mt < 2; mt++)
                    ldsm_x4(a[mt][0], a[mt][1], a[mt][2], a[mt][3],
                            bA + aoffl + mt * 16 * 80 + k16 * 32);
                uint32_t b[4][4];
                #pragma unroll
                for (int nt2 = 0; nt2 < 4; nt2++)
                    ldsm_x4_t(b[nt2][0], b[nt2][1], b[nt2][2], b[nt2][3],
                              bB + boffl + k16 * 16 * 272 + nt2 * 16 * 2);
                #pragma unroll
                for (int mt = 0; mt < 2; mt++)
                    #pragma unroll
                    for (int nt = 0; nt < 8; nt++)
                        mma16816(acc[mt][nt], a[mt], &b[nt >> 1][(nt & 1) * 2]);
            }
        }
    };

    ldchunk(0, 0); CP_COMMIT();
    #pragma unroll 1
    for (int it = 0; it < 8; it++) {
        CP_WAIT0();
        __syncthreads();
        if (it + 1 < 8) { ldchunk(it + 1, (it + 1) & 1); CP_COMMIT(); }
        compute(it & 1);
    }

    #pragma unroll
    for (int mt = 0; mt < 2; mt++) {
        #pragma unroll
        for (int hf = 0; hf < 2; hf++) {
            const int m = m0 + warp_m + mt * 16 + (lane >> 2) + hf * 8;
            float rv = 0.f;
            if (epi == 5) rv = 1.0f / den[m];
            #pragma unroll
            for (int nt = 0; nt < 8; nt++) {
                const int n = n0 + warp_n + nt * 8 + (lane & 3) * 2;
                float v0 = acc[mt][nt][hf * 2 + 0];
                float v1 = acc[mt][nt][hf * 2 + 1];
                if (epi == 5) {
                    v0 = v0 * rv + bias[n];
                    v1 = v1 * rv + bias[n + 1];
                }
                if (Cf)
                    *(float2*)&Cf[(long)m * 256 + n] = make_float2(v0, v1);
                if (Ch) {
                    unsigned hp, lp;
                    packHL(v0, v1, hp, lp);
                    *(unsigned*)&Ch[(long)m * 256 + n] = hp;
                    *(unsigned*)&Cl[(long)m * 256 + n] = lp;
                }
            }
        }
    }
}

// ===========================================================================
// Elementwise kernels
// ===========================================================================
__global__ void clear_kernel() {
    if (threadIdx.x < BATCH)
        ((unsigned*)(g_f + F_KMAX))[threadIdx.x] = 0u;
}

__global__ __launch_bounds__(256)
void conv4(const float* __restrict__ in0, const float* __restrict__ in1,
           __nv_bfloat16* __restrict__ outBase, long stride, long n4) {
    const float* in = (blockIdx.z == 0) ? in0 : in1;
    __nv_bfloat16* h = outBase + (long)blockIdx.z * 2 * stride;
    __nv_bfloat16* l = h + stride;
    long i = (long)blockIdx.x * 256 + threadIdx.x;
    if (i < n4) {
        float4 x = ((const float4*)in)[i];
        float xs[4] = {x.x, x.y, x.z, x.w};
        unsigned short hh[4], ll[4];
        #pragma unroll
        for (int j = 0; j < 4; j++) {
            __nv_bfloat16 hi = __float2bfloat16(xs[j]);
            hh[j] = __bfloat16_as_ushort(hi);
            ll[j] = __bfloat16_as_ushort(__float2bfloat16(xs[j] - __bfloat162float(hi)));
        }
        ((uint2*)h)[i] = make_uint2((unsigned)hh[0] | ((unsigned)hh[1] << 16),
                                    (unsigned)hh[2] | ((unsigned)hh[3] << 16));
        ((uint2*)l)[i] = make_uint2((unsigned)ll[0] | ((unsigned)ll[1] << 16),
                                    (unsigned)ll[2] | ((unsigned)ll[3] << 16));
    }
}

__global__ __launch_bounds__(256)
void tconvW(const float* __restrict__ w0, const float* __restrict__ w1) {
    __shared__ float t[32][33];
    const int zz = blockIdx.z;
    const float* in = (zz == 0) ? w0 : w1;
    __nv_bfloat16* oh = g_b + ((zz == 0) ? B_WQTH : B_WKTH);
    __nv_bfloat16* ol = g_b + ((zz == 0) ? B_WQTL : B_WKTL);
    const int r0 = blockIdx.x * 32, c0 = blockIdx.y * 32;
    const int tx = threadIdx.x, ty = threadIdx.y;
    #pragma unroll
    for (int d = 0; d < 4; d++)
        t[ty + 8 * d][tx] = in[(long)(r0 + ty + 8 * d) * 256 + c0 + tx];
    __syncthreads();
    #pragma unroll
    for (int d = 0; d < 4; d++) {
        const int cc = c0 + ty + 8 * d;
        float x = t[tx][ty + 8 * d];
        __nv_bfloat16 hi = __float2bfloat16(x);
        long o = (long)cc * 256 + r0 + tx;
        oh[o] = hi;
        ol[o] = __float2bfloat16(x - __bfloat162float(hi));
    }
}

// bias2[d] = sum_j bv[j] * Wo[j][d] + bo[d]   (grid 8 x 32 threads-col blocks)
__global__ __launch_bounds__(256)
void bias2_kernel(const float* __restrict__ bv, const float* __restrict__ Wo,
                  const float* __restrict__ bo) {
    const int d = blockIdx.x * 256 + threadIdx.x;
    if (d < 256) {
        float s = bo[d];
        for (int j = 0; j < 256; j++)
            s += bv[j] * Wo[(long)j * 256 + d];
        g_f[F_BIAS2 + d] = s;
    }
}

// kvsU reduce: 8 split-K partials -> row-major hi/lo
__global__ __launch_bounds__(256)
void kvsured() {
    const int b = blockIdx.y, m = blockIdx.x, c = threadIdx.x;
    const float* p = g_f + F_PART + (long)b * 8 * SZW + (long)m * 256 + c;
    float s = 0.f;
    #pragma unroll
    for (int spl = 0; spl < 8; spl++)
        s += p[(long)spl * SZW];
    __nv_bfloat16 hi = __float2bfloat16(s);
    const long o = (long)b * SZW + (long)m * 256 + c;
    g_b[B_KVUH + o] = hi;
    g_b[B_KVUL + o] = __float2bfloat16(s - __bfloat162float(hi));
}

__global__ __launch_bounds__(256) void kp_kernel() {
    const int row = blockIdx.x;
    const int b   = row >> 11;
    const int t   = threadIdx.x;
    const long base = (long)row * MFEAT;
    const float x = __bfloat162float(g_b[B_KSH + base + t])
                  + __bfloat162float(g_b[B_KSL + base + t]);
    const float xp = g_f[F_XK + base + t];
    __shared__ float sm8[8];
    const float diag = 0.5f * blockSum256(x * x, sm8);
    const float mx = ord_dec(((const unsigned*)(g_f + F_KMAX))[b]);
    const float kp = 0.0625f * (expf(xp - diag - mx) + 1e-6f);
    __nv_bfloat16 hi = __float2bfloat16(kp);
    g_b[B_KPH + base + t] = hi;
    g_b[B_KPL + base + t] = __float2bfloat16(kp - __bfloat162float(hi));
}

__global__ __launch_bounds__(256) void ksump_kernel() {
    const int b = blockIdx.y, chunk = blockIdx.x, m = threadIdx.x;
    const long baseh = B_KPH + (long)b * L_SEQ * MFEAT;
    const long basel = B_KPL + (long)b * L_SEQ * MFEAT;
    float s = 0.f;
    const int r0 = chunk * 32;
    #pragma unroll 4
    for (int r = 0; r < 32; r++) {
        const long o = (long)(r0 + r) * MFEAT + m;
        s += __bfloat162float(g_b[baseh + o]) + __bfloat162float(g_b[basel + o]);
    }
    g_f[F_KSUMP + ((long)b * KCH + chunk) * MFEAT + m] = s;
}

__global__ __launch_bounds__(256) void ksumfold_kernel() {
    const int b = blockIdx.x, t = threadIdx.x;
    float s = 0.f;
    #pragma unroll
    for (int c = 0; c < KCH; c++)
        s += g_f[F_KSUMP + ((long)b * KCH + c) * MFEAT + t];
    g_f[F_KSUM + (long)b * MFEAT + t] = s;
}

__global__ __launch_bounds__(256) void qpden_kernel() {
    const int row = blockIdx.x;
    const int b   = row >> 11;
    const int t   = threadIdx.x;
    const long base = (long)row * MFEAT;
    const float x = __bfloat162float(g_b[B_QSH + base + t])
                  + __bfloat162float(g_b[B_QSL + base + t]);
    const float xp = g_f[F_XQ + base + t];
    __shared__ float sm8[8];
    const float diag = 0.5f * blockSum256(x * x, sm8);
    const float mx   = blockMax256(xp, sm8);
    const float qp = 0.0625f * (expf(xp - diag - mx) + 1e-6f);
    __nv_bfloat16 hi = __float2bfloat16(qp);
    g_b[B_QPH + base + t] = hi;
    g_b[B_QPL + base + t] = __float2bfloat16(qp - __bfloat162float(hi));
    const float ks = g_f[F_KSUM + (long)b * MFEAT + t];
    const float den = blockSum256(qp * ks, sm8);
    if (t == 0) g_f[F_DEN + row] = den;
}

// ===========================================================================
// launch — fork/join across two streams
// ===========================================================================
extern "C" void kernel_launch(void* const* d_in, const int* in_sizes, int n_in,
                              void* d_out, int out_size)
{
    const float* query = (const float*)d_in[0];
    const float* key   = (const float*)d_in[1];
    const float* value = (const float*)d_in[2];
    const float* Wq = (const float*)d_in[4];
    const float* bq = (const float*)d_in[5];
    const float* Wk = (const float*)d_in[6];
    const float* bk = (const float*)d_in[7];
    const float* Wv = (const float*)d_in[8];
    const float* bv = (const float*)d_in[9];
    const float* Wo = (const float*)d_in[10];
    const float* bo = (const float*)d_in[11];
    const float* proj = (const float*)d_in[12];
    const float* pos  = (const float*)d_in[13];
    float* out = (float*)d_out;

    void* fp = nullptr; cudaGetSymbolAddress(&fp, g_f);
    void* bp = nullptr; cudaGetSymbolAddress(&bp, g_b);
    float* F = (float*)fp;
    __nv_bfloat16* Bp = (__nv_bfloat16*)bp;

    static cudaStream_t s2 = nullptr;
    static cudaEvent_t evF, evW, evW2, evK, evD;
    if (!s2) {
        cudaFuncSetAttribute(mma_nt, cudaFuncAttributeMaxDynamicSharedMemorySize, 81920);
        cudaFuncSetAttribute(mma_tn, cudaFuncAttributeMaxDynamicSharedMemorySize, 69632);
        cudaFuncSetAttribute(mma_nn, cudaFuncAttributeMaxDynamicSharedMemorySize, 75776);
        cudaStreamCreateWithFlags(&s2, cudaStreamNonBlocking);
        cudaEventCreateWithFlags(&evF,  cudaEventDisableTiming);
        cudaEventCreateWithFlags(&evW,  cudaEventDisableTiming);
        cudaEventCreateWithFlags(&evW2, cudaEventDisableTiming);
        cudaEventCreateWithFlags(&evK,  cudaEventDisableTiming);
        cudaEventCreateWithFlags(&evD,  cudaEventDisableTiming);
    }
    const int SM_NT = 81920, SM_TN = 69632, SM_NN = 75776;
    dim3 tb(32, 8);

    // ---- main stream first node, then fork s2 off it ----
    clear_kernel<<<1, 32>>>();
    cudaEventRecord(evF, 0);

    // ---- stream 2: weight chain ----
    cudaStreamWaitEvent(s2, evF, 0);
    tconvW<<<dim3(8, 8, 2), tb, 0, s2>>>(Wq, Wk);
    cudaEventRecord(evW, s2);
    conv4<<<dim3(64, 1, 2), 256, 0, s2>>>(Wv, Wo, Bp + B_WVINH, SZW, SZW / 4);
    // W2 = Wv @ Wo  (NN, tiny)
    mma_nn<<<dim3(2, 2, 1), 256, SM_NN, s2>>>(
        Bp + B_WVINH, Bp + B_WVINL, Bp + B_WOINH, Bp + B_WOINL,
        nullptr, Bp + B_W2H, Bp + B_W2L,
        nullptr, nullptr, 0, 0, 0, 0, 0);
    bias2_kernel<<<1, 256, 0, s2>>>(bv, Wo, bo);
    cudaEventRecord(evW2, s2);

    // ---- main stream: input conversions ----
    conv4<<<dim3((unsigned)(SZB / 1024), 1, 2), 256>>>(query, key, Bp + B_QINH, SZB, SZB / 4);
    conv4<<<dim3((unsigned)(SZB / 1024), 1, 1), 256>>>(value, value, Bp + B_VINH, SZB, SZB / 4);
    conv4<<<dim3(64, 1, 1), 256>>>(proj, proj, Bp + B_PRJH, SZW, SZW / 4);

    // ---- main: q/k projections (needs WQT/WKT) ----
    cudaStreamWaitEvent(0, evW, 0);
    mma_nt<<<dim3(2, 64, 2), 256, SM_NT>>>(
        Bp + B_QINH, Bp + B_QINL, Bp + B_WQTH, Bp + B_WQTL,
        nullptr, Bp + B_QSH, Bp + B_QSL,
        bq, bk, pos,
        2 * SZB, 2 * SZW, 2 * SZB, 2, -1);

    // xq/xk: z=0 -> XQ, z=1 -> XK (+per-batch max)
    mma_nt<<<dim3(2, 64, 2), 256, SM_NT>>>(
        Bp + B_QSH, Bp + B_QSL, Bp + B_PRJH, Bp + B_PRJL,
        F + F_XQ, nullptr, nullptr,
        nullptr, nullptr, nullptr,
        2 * SZB, 0, SZB, 0, 1);

    kp_kernel<<<NROWS, 256>>>();
    cudaEventRecord(evK, 0);

    // ---- stream 2: ksum + qpden (overlap with kvsU GEMM + kvsW) ----
    cudaStreamWaitEvent(s2, evK, 0);
    ksump_kernel<<<dim3(KCH, BATCH), 256, 0, s2>>>();
    ksumfold_kernel<<<BATCH, 256, 0, s2>>>();
    qpden_kernel<<<NROWS, 256, 0, s2>>>();
    cudaEventRecord(evD, s2);

    // ---- main: kvsU = kp^T @ value  (TN, split-K 8) ----
    mma_tn<<<dim3(2, 2, 32), 256, SM_TN>>>(
        Bp + B_KPH, Bp + B_KPL, Bp + B_VINH, Bp + B_VINL,
        F + F_PART,
        (long)L_SEQ * MFEAT, (long)256 * MFEAT,
        (long)L_SEQ * 256,  (long)256 * 256,
        (long)8 * SZW, SZW);
    kvsured<<<dim3(256, BATCH), 256>>>();

    // ---- main: kvsW = kvsU @ W2  (pure GEMM — only needs W2, not den) ----
    cudaStreamWaitEvent(0, evW2, 0);
    mma_nn<<<dim3(2, 2, 4), 256, SM_NN>>>(
        Bp + B_KVUH, Bp + B_KVUL, Bp + B_W2H, Bp + B_W2L,
        nullptr, Bp + B_KVSWH, Bp + B_KVSWL,
        nullptr, nullptr,
        SZW, 0, SZW, 0, 0);

    // ---- main: out = (qp @ kvsW)/den + (bvWo + bo)  (NN, batched) ----
    cudaStreamWaitEvent(0, evD, 0);
    mma_nn<<<dim3(2, 16, 4), 256, SM_NN>>>(
        Bp + B_QPH, Bp + B_QPL, Bp + B_KVSWH, Bp + B_KVSWL,
        out, nullptr, nullptr,
        F + F_BIAS2, F + F_DEN,
        (long)L_SEQ * 256, SZW, (long)L_SEQ * 256, L_SEQ, 5);
}

// round 16
// speedup vs baseline: 1.0603x; 1.0603x over previous
#include <cuda_runtime.h>
#include <cuda_bf16.h>
#include <math.h>
#include <stdint.h>

#define L_SEQ   2048
#define DMODEL  256
#define BATCH   4
#define MFEAT   256
#define NROWS   8192

// ===========================================================================
// Scratch
// ===========================================================================
static constexpr long SZB = (long)NROWS * DMODEL;   // 2,097,152
static constexpr long SZW = 65536;
static constexpr int  KCH = 64;

// f32 scratch
static constexpr long F_XQ    = 0;
static constexpr long F_XK    = F_XQ + SZB;
static constexpr long F_PART  = F_XK + SZB;                 // 32 * SZW
static constexpr long F_DEN   = F_PART + SZB;
static constexpr long F_KSUMP = F_DEN + NROWS;
static constexpr long F_KSUM  = F_KSUMP + (long)BATCH * KCH * MFEAT;
static constexpr long F_BIAS2 = F_KSUM + (long)BATCH * MFEAT;   // bvWo + bo
static constexpr long F_KMAX  = F_BIAS2 + MFEAT;
static constexpr long F_TOTAL = F_KMAX + 16;
__device__ float g_f[F_TOTAL];

// bf16 scratch
static constexpr long B_QINH = 0;
static constexpr long B_QINL = B_QINH + SZB;
static constexpr long B_KINH = B_QINL + SZB;
static constexpr long B_KINL = B_KINH + SZB;
static constexpr long B_VINH = B_KINL + SZB;
static constexpr long B_VINL = B_VINH + SZB;
static constexpr long B_VW2H = B_VINL + SZB;    // value @ W2 (bf16 hi/lo)
static constexpr long B_VW2L = B_VW2H + SZB;
static constexpr long B_QSH  = B_VW2L + SZB;
static constexpr long B_QSL  = B_QSH + SZB;
static constexpr long B_KSH  = B_QSL + SZB;
static constexpr long B_KSL  = B_KSH + SZB;
static constexpr long B_QPH  = B_KSL + SZB;
static constexpr long B_QPL  = B_QPH + SZB;
static constexpr long B_KPH  = B_QPL + SZB;
static constexpr long B_KPL  = B_KPH + SZB;
static constexpr long B_WQTH = B_KPL + SZB;
static constexpr long B_WQTL = B_WQTH + SZW;
static constexpr long B_WKTH = B_WQTL + SZW;
static constexpr long B_WKTL = B_WKTH + SZW;
static constexpr long B_PRJH = B_WKTL + SZW;
static constexpr long B_PRJL = B_PRJH + SZW;
static constexpr long B_WVINH = B_PRJL + SZW;   // conv4 z=0
static constexpr long B_WVINL = B_WVINH + SZW;
static constexpr long B_WOINH = B_WVINL + SZW;  // conv4 z=1
static constexpr long B_WOINL = B_WOINH + SZW;
static constexpr long B_W2H  = B_WOINL + SZW;
static constexpr long B_W2L  = B_W2H + SZW;
static constexpr long B_KVSWH = B_W2L + SZW;    // 4*SZW (kvsW = kp^T @ valueW2)
static constexpr long B_KVSWL = B_KVSWH + 4 * SZW;
static constexpr long B_TOTAL = B_KVSWL + 4 * SZW;
__device__ __nv_bfloat16 g_b[B_TOTAL];

// ===========================================================================
// Helpers
// ===========================================================================
__device__ __forceinline__ uint32_t smem_u32(const void* p) {
    uint32_t a;
    asm("{ .reg .u64 t; cvta.to.shared.u64 t, %1; cvt.u32.u64 %0, t; }"
        : "=r"(a) : "l"(p));
    return a;
}
__device__ __forceinline__ void cp16(uint32_t dst, const void* src) {
    asm volatile("cp.async.cg.shared.global [%0], [%1], 16;"
                 :: "r"(dst), "l"(src) : "memory");
}
#define CP_COMMIT()  asm volatile("cp.async.commit_group;" ::: "memory")
#define CP_WAIT0()   asm volatile("cp.async.wait_group 0;" ::: "memory")

__device__ __forceinline__ void ldsm_x4(uint32_t& r0, uint32_t& r1,
                                        uint32_t& r2, uint32_t& r3, uint32_t addr) {
    asm volatile("ldmatrix.sync.aligned.m8n8.x4.shared.b16 {%0,%1,%2,%3}, [%4];"
                 : "=r"(r0), "=r"(r1), "=r"(r2), "=r"(r3) : "r"(addr));
}
__device__ __forceinline__ void ldsm_x4_t(uint32_t& r0, uint32_t& r1,
                                          uint32_t& r2, uint32_t& r3, uint32_t addr) {
    asm volatile("ldmatrix.sync.aligned.m8n8.x4.trans.shared.b16 {%0,%1,%2,%3}, [%4];"
                 : "=r"(r0), "=r"(r1), "=r"(r2), "=r"(r3) : "r"(addr));
}
__device__ __forceinline__ void mma16816(float* d, const uint32_t* a, const uint32_t* b) {
    asm volatile("mma.sync.aligned.m16n8k16.row.col.f32.bf16.bf16.f32 "
                 "{%0,%1,%2,%3}, {%4,%5,%6,%7}, {%8,%9}, {%0,%1,%2,%3};"
                 : "+f"(d[0]), "+f"(d[1]), "+f"(d[2]), "+f"(d[3])
                 : "r"(a[0]), "r"(a[1]), "r"(a[2]), "r"(a[3]), "r"(b[0]), "r"(b[1]));
}
__device__ __forceinline__ unsigned ord_enc(float f) {
    unsigned u = __float_as_uint(f);
    return (u & 0x80000000u) ? ~u : (u | 0x80000000u);
}
__device__ __forceinline__ float ord_dec(unsigned u) {
    return __uint_as_float((u & 0x80000000u) ? (u & 0x7fffffffu) : ~u);
}
__device__ __forceinline__ float blockSum256(float v, float* sm8) {
    #pragma unroll
    for (int o = 16; o; o >>= 1) v += __shfl_xor_sync(0xffffffffu, v, o);
    if ((threadIdx.x & 31) == 0) sm8[threadIdx.x >> 5] = v;
    __syncthreads();
    float s = 0.f;
    #pragma unroll
    for (int i = 0; i < 8; i++) s += sm8[i];
    __syncthreads();
    return s;
}
__device__ __forceinline__ float blockMax256(float v, float* sm8) {
    #pragma unroll
    for (int o = 16; o; o >>= 1) v = fmaxf(v, __shfl_xor_sync(0xffffffffu, v, o));
    if ((threadIdx.x & 31) == 0) sm8[threadIdx.x >> 5] = v;
    __syncthreads();
    float s = sm8[0];
    #pragma unroll
    for (int i = 1; i < 8; i++) s = fmaxf(s, sm8[i]);
    __syncthreads();
    return s;
}
__device__ __forceinline__ void packHL(float v0, float v1,
                                       unsigned& hp, unsigned& lp) {
    __nv_bfloat16 h0 = __float2bfloat16(v0);
    __nv_bfloat16 h1 = __float2bfloat16(v1);
    float l0 = v0 - __bfloat162float(h0);
    float l1 = v1 - __bfloat162float(h1);
    hp = ((unsigned)__bfloat16_as_ushort(h1) << 16) | __bfloat16_as_ushort(h0);
    lp = ((unsigned)__bfloat16_as_ushort(__float2bfloat16(l1)) << 16)
       | __bfloat16_as_ushort(__float2bfloat16(l0));
}

// ===========================================================================
// NT GEMM (bf16 3-pass, verified): 256 thr, 8 warps (4Mx2N), K=256.
//   epiMode: 0 none, 2 +bias+rotary+0.25
//   domaxZ: if z == domaxZ, atomicMax raw acc into g_f[F_KMAX + m0>>11]
// Stage (stride 40960): Ah@0 Al@10240 Bh@20480 Bl@30720 (80B rows)
// ===========================================================================
__global__ __launch_bounds__(256, 2)
void mma_nt(const __nv_bfloat16* __restrict__ Ah, const __nv_bfloat16* __restrict__ Al,
            const __nv_bfloat16* __restrict__ Bh, const __nv_bfloat16* __restrict__ Bl,
            float* __restrict__ Cf, __nv_bfloat16* __restrict__ Ch,
            __nv_bfloat16* __restrict__ Cl,
            const float* __restrict__ bias0, const float* __restrict__ bias1,
            const float* __restrict__ pos,
            long sAb, long sBb, long sCb,
            int epiMode, int domaxZ)
{
    extern __shared__ __align__(16) char smemBuf[];

    const int tid  = threadIdx.x;
    const int wid  = tid >> 5;
    const int lane = tid & 31;
    const int warp_m = (wid >> 1) * 32;
    const int warp_n = (wid & 1) * 64;

    const int z = blockIdx.z;
    const float* bias = (z == 0) ? bias0 : bias1;
    if (Cf) Cf += (long)z * sCb;
    if (Ch) { Ch += (long)z * sCb; Cl += (long)z * sCb; }

    const int m0 = blockIdx.y * 128;
    const int n0 = blockIdx.x * 128;
    const uint32_t sbase = smem_u32(smemBuf);

    const int lrow = tid >> 1;
    const int lcol = (tid & 1) * 16;
    const long zA = (long)z * sAb;
    const long zB = (long)z * sBb;
    const __nv_bfloat16* aH = Ah + zA + (long)(m0 + lrow) * 256 + lcol;
    const __nv_bfloat16* aL = Al + zA + (long)(m0 + lrow) * 256 + lcol;
    const __nv_bfloat16* bH = Bh + zB + (long)(n0 + lrow) * 256 + lcol;
    const __nv_bfloat16* bL = Bl + zB + (long)(n0 + lrow) * 256 + lcol;
    const uint32_t dstA = sbase + lrow * 80 + (tid & 1) * 32;
    const uint32_t dstB = dstA + 20480;

    auto ldchunk = [&](int ck, int slot) {
        const int kk = ck * 32;
        const uint32_t so = slot * 40960;
        cp16(dstA + so,              aH + kk);
        cp16(dstA + so + 16,         aH + kk + 8);
        cp16(dstA + so + 10240,      aL + kk);
        cp16(dstA + so + 10240 + 16, aL + kk + 8);
        cp16(dstB + so,              bH + kk);
        cp16(dstB + so + 16,         bH + kk + 8);
        cp16(dstB + so + 10240,      bL + kk);
        cp16(dstB + so + 10240 + 16, bL + kk + 8);
    };

    const uint32_t aoffl = (warp_m + (lane & 15)) * 80 + (lane >> 4) * 16;
    const uint32_t boffl = (warp_n + (lane & 7) + ((lane >> 4) & 1) * 8) * 80
                         + ((lane >> 3) & 1) * 16;

    float acc[2][8][4] = {};

    auto compute = [&](int slot) {
        const uint32_t base = sbase + slot * 40960;
        #pragma unroll
        for (int pass = 0; pass < 3; pass++) {
            const uint32_t bA = base + ((pass == 2) ? 10240u : 0u);
            const uint32_t bB = base + 20480u + ((pass == 1) ? 10240u : 0u);
            #pragma unroll
            for (int k16 = 0; k16 < 2; k16++) {
                uint32_t a[2][4];
                #pragma unroll
                for (int mt = 0; mt < 2; mt++)
                    ldsm_x4(a[mt][0], a[mt][1], a[mt][2], a[mt][3],
                            bA + aoffl + mt * 16 * 80 + k16 * 32);
                uint32_t b[4][4];
                #pragma unroll
                for (int nt2 = 0; nt2 < 4; nt2++)
                    ldsm_x4(b[nt2][0], b[nt2][1], b[nt2][2], b[nt2][3],
                            bB + boffl + nt2 * 16 * 80 + k16 * 32);
                #pragma unroll
                for (int mt = 0; mt < 2; mt++)
                    #pragma unroll
                    for (int nt = 0; nt < 8; nt++)
                        mma16816(acc[mt][nt], a[mt], &b[nt >> 1][(nt & 1) * 2]);
            }
        }
    };

    ldchunk(0, 0); CP_COMMIT();
    #pragma unroll 1
    for (int it = 0; it < 8; it++) {
        CP_WAIT0();
        __syncthreads();
        if (it + 1 < 8) { ldchunk(it + 1, (it + 1) & 1); CP_COMMIT(); }
        compute(it & 1);
    }

    if (z == domaxZ) {
        float mx = -3.402823466e38f;
        #pragma unroll
        for (int mt = 0; mt < 2; mt++)
            #pragma unroll
            for (int nt = 0; nt < 8; nt++)
                #pragma unroll
                for (int q = 0; q < 4; q++)
                    mx = fmaxf(mx, acc[mt][nt][q]);
        __syncthreads();
        mx = blockMax256(mx, (float*)smemBuf);
        if (tid == 0)
            atomicMax((unsigned*)(g_f + F_KMAX) + (m0 >> 11), ord_enc(mx));
    }

    #pragma unroll
    for (int mt = 0; mt < 2; mt++) {
        #pragma unroll
        for (int hf = 0; hf < 2; hf++) {
            const int m = m0 + warp_m + mt * 16 + (lane >> 2) + hf * 8;
            const int l = m & (L_SEQ - 1);
            #pragma unroll
            for (int nt = 0; nt < 8; nt++) {
                const int n = n0 + warp_n + nt * 8 + (lane & 3) * 2;
                float v0 = acc[mt][nt][hf * 2 + 0];
                float v1 = acc[mt][nt][hf * 2 + 1];
                if (epiMode == 2) {
                    v0 += bias[n]; v1 += bias[n + 1];
                    const float sn = pos[(long)l * DMODEL + n];
                    const float cs = pos[(long)l * DMODEL + n + 1];
                    const float q0 = v0 * cs - v1 * sn;
                    const float q1 = v1 * cs + v0 * sn;
                    v0 = q0 * 0.25f; v1 = q1 * 0.25f;
                }
                if (Cf)
                    *(float2*)&Cf[(long)m * 256 + n] = make_float2(v0, v1);
                if (Ch) {
                    unsigned hp, lp;
                    packHL(v0, v1, hp, lp);
                    *(unsigned*)&Ch[(long)m * 256 + n] = hp;
                    *(unsigned*)&Cl[(long)m * 256 + n] = lp;
                }
            }
        }
    }
}

// ===========================================================================
// TN GEMM (bf16 3-pass, verified): A [K,M], B [K,N], ldmatrix .trans.
//   Split-K: z = bz*8+sp, 256 K-rows/split; f32 out.
// Stage (stride 34816): Ah@0 Al@8704 Bh@17408 Bl@26112 (272B rows)
// ===========================================================================
__global__ __launch_bounds__(256, 2)
void mma_tn(const __nv_bfloat16* __restrict__ Ah, const __nv_bfloat16* __restrict__ Al,
            const __nv_bfloat16* __restrict__ Bh, const __nv_bfloat16* __restrict__ Bl,
            float* __restrict__ Cf,
            long sAb, long sAs, long sBb, long sBs, long sCb, long sCs)
{
    extern __shared__ __align__(16) char smemBuf[];

    const int tid  = threadIdx.x;
    const int wid  = tid >> 5;
    const int lane = tid & 31;
    const int warp_m = (wid >> 1) * 32;
    const int warp_n = (wid & 1) * 64;

    const int z  = blockIdx.z;
    const int bz = z >> 3, sp = z & 7;
    const long aoff = (long)bz * sAb + (long)sp * sAs;
    const long boff = (long)bz * sBb + (long)sp * sBs;
    Cf += (long)bz * sCb + (long)sp * sCs;

    const int m0 = blockIdx.y * 128;
    const int n0 = blockIdx.x * 128;
    const uint32_t sbase = smem_u32(smemBuf);

    const int lrow = tid >> 3;
    const int lcol = (tid & 7) * 16;
    const __nv_bfloat16* aH = Ah + aoff + (long)lrow * 256 + m0 + lcol;
    const __nv_bfloat16* aL = Al + aoff + (long)lrow * 256 + m0 + lcol;
    const __nv_bfloat16* bH = Bh + boff + (long)lrow * 256 + n0 + lcol;
    const __nv_bfloat16* bL = Bl + boff + (long)lrow * 256 + n0 + lcol;
    const uint32_t dstA = sbase + lrow * 272 + (tid & 7) * 32;
    const uint32_t dstB = dstA + 17408;

    auto ldchunk = [&](int ck, int slot) {
        const long kk = (long)ck * 32 * 256;
        const uint32_t so = slot * 34816;
        cp16(dstA + so,             aH + kk);
        cp16(dstA + so + 16,        aH + kk + 8);
        cp16(dstA + so + 8704,      aL + kk);
        cp16(dstA + so + 8704 + 16, aL + kk + 8);
        cp16(dstB + so,             bH + kk);
        cp16(dstB + so + 16,        bH + kk + 8);
        cp16(dstB + so + 8704,      bL + kk);
        cp16(dstB + so + 8704 + 16, bL + kk + 8);
    };

    const uint32_t aoffl = ((lane & 7) + ((lane >> 4) & 1) * 8) * 272
                         + (warp_m + ((lane >> 3) & 1) * 8) * 2;
    const uint32_t boffl = ((lane & 7) + ((lane >> 3) & 1) * 8) * 272
                         + (warp_n + ((lane >> 4) & 1) * 8) * 2;

    float acc[2][8][4] = {};

    auto compute = [&](int slot) {
        const uint32_t base = sbase + slot * 34816;
        #pragma unroll
        for (int pass = 0; pass < 3; pass++) {
            const uint32_t bA = base + ((pass == 2) ? 8704u : 0u);
            const uint32_t bB = base + 17408u + ((pass == 1) ? 8704u : 0u);
            #pragma unroll
            for (int k16 = 0; k16 < 2; k16++) {
                uint32_t a[2][4];
                #pragma unroll
                for (int mt = 0; mt < 2; mt++)
                    ldsm_x4_t(a[mt][0], a[mt][1], a[mt][2], a[mt][3],
                              bA + aoffl + k16 * 16 * 272 + mt * 16 * 2);
                uint32_t b[4][4];
                #pragma unroll
                for (int nt2 = 0; nt2 < 4; nt2++)
                    ldsm_x4_t(b[nt2][0], b[nt2][1], b[nt2][2], b[nt2][3],
                              bB + boffl + k16 * 16 * 272 + nt2 * 16 * 2);
                #pragma unroll
                for (int mt = 0; mt < 2; mt++)
                    #pragma unroll
                    for (int nt = 0; nt < 8; nt++)
                        mma16816(acc[mt][nt], a[mt], &b[nt >> 1][(nt & 1) * 2]);
            }
        }
    };

    ldchunk(0, 0); CP_COMMIT();
    #pragma unroll 1
    for (int it = 0; it < 8; it++) {
        CP_WAIT0();
        __syncthreads();
        if (it + 1 < 8) { ldchunk(it + 1, (it + 1) & 1); CP_COMMIT(); }
        compute(it & 1);
    }

    #pragma unroll
    for (int mt = 0; mt < 2; mt++)
        #pragma unroll
        for (int hf = 0; hf < 2; hf++) {
            const int m = m0 + warp_m + mt * 16 + (lane >> 2) + hf * 8;
            #pragma unroll
            for (int nt = 0; nt < 8; nt++) {
                const int n = n0 + warp_n + nt * 8 + (lane & 3) * 2;
                *(float2*)&Cf[(long)m * 256 + n] =
                    make_float2(acc[mt][nt][hf * 2], acc[mt][nt][hf * 2 + 1]);
            }
        }
}

// ===========================================================================
// NN GEMM (bf16 3-pass): A [M,K=256] row-major, B [K=256,N] row-major.
//   epi: 0 none, 5 = /den[m] + bias[n]
// Stage (stride 37888): Ah@0 Al@10240 Bh@20480 Bl@29184
// ===========================================================================
__global__ __launch_bounds__(256, 2)
void mma_nn(const __nv_bfloat16* __restrict__ Ah, const __nv_bfloat16* __restrict__ Al,
            const __nv_bfloat16* __restrict__ Bh, const __nv_bfloat16* __restrict__ Bl,
            float* __restrict__ Cf, __nv_bfloat16* __restrict__ Ch,
            __nv_bfloat16* __restrict__ Cl,
            const float* __restrict__ bias, const float* __restrict__ den,
            long sAb, long sBb, long sCb, long sDen, int epi)
{
    extern __shared__ __align__(16) char smemBuf[];   // 2 x 37888

    const int tid  = threadIdx.x;
    const int wid  = tid >> 5;
    const int lane = tid & 31;
    const int warp_m = (wid >> 1) * 32;
    const int warp_n = (wid & 1) * 64;

    const int z = blockIdx.z;
    Ah += (long)z * sAb; Al += (long)z * sAb;
    Bh += (long)z * sBb; Bl += (long)z * sBb;
    if (Cf) Cf += (long)z * sCb;
    if (Ch) { Ch += (long)z * sCb; Cl += (long)z * sCb; }
    if (epi == 5) den += (long)z * sDen;

    const int m0 = blockIdx.y * 128;
    const int n0 = blockIdx.x * 128;
    const uint32_t sbase = smem_u32(smemBuf);

    const int lrowA = tid >> 1;
    const __nv_bfloat16* aH = Ah + (long)(m0 + lrowA) * 256 + (tid & 1) * 16;
    const __nv_bfloat16* aL = Al + (long)(m0 + lrowA) * 256 + (tid & 1) * 16;
    const uint32_t dstA = sbase + lrowA * 80 + (tid & 1) * 32;
    const int lrowB = tid >> 3;
    const __nv_bfloat16* bH = Bh + (long)lrowB * 256 + n0 + (tid & 7) * 16;
    const __nv_bfloat16* bL = Bl + (long)lrowB * 256 + n0 + (tid & 7) * 16;
    const uint32_t dstB = sbase + 20480 + lrowB * 272 + (tid & 7) * 32;

    auto ldchunk = [&](int ck, int slot) {
        const int  kkA = ck * 32;
        const long kkB = (long)ck * 32 * 256;
        const uint32_t so = slot * 37888;
        cp16(dstA + so,              aH + kkA);
        cp16(dstA + so + 16,         aH + kkA + 8);
        cp16(dstA + so + 10240,      aL + kkA);
        cp16(dstA + so + 10240 + 16, aL + kkA + 8);
        cp16(dstB + so,             bH + kkB);
        cp16(dstB + so + 16,        bH + kkB + 8);
        cp16(dstB + so + 8704,      bL + kkB);
        cp16(dstB + so + 8704 + 16, bL + kkB + 8);
    };

    const uint32_t aoffl = (warp_m + (lane & 15)) * 80 + (lane >> 4) * 16;
    const uint32_t boffl = ((lane & 7) + ((lane >> 3) & 1) * 8) * 272
                         + (warp_n + ((lane >> 4) & 1) * 8) * 2;

    float acc[2][8][4] = {};

    auto compute = [&](int slot) {
        const uint32_t base = sbase + slot * 37888;
        #pragma unroll
        for (int pass = 0; pass < 3; pass++) {
            const uint32_t bA = base + ((pass == 2) ? 10240u : 0u);
            const uint32_t bB = base + 20480u + ((pass == 1) ? 8704u : 0u);
            #pragma unroll
            for (int k16 = 0; k16 < 2; k16++) {
                uint32_t a[2][4];
                #pragma unroll
                for (int mt = 0; mt < 2; mt++)
                    ldsm_x4(a[mt][0], a[mt][1], a[mt][2], a[mt][3],
                            bA + aoffl + mt * 16 * 80 + k16 * 32);
                uint32_t b[4][4];
                #pragma unroll
                for (int nt2 = 0; nt2 < 4; nt2++)
                    ldsm_x4_t(b[nt2][0], b[nt2][1], b[nt2][2], b[nt2][3],
                              bB + boffl + k16 * 16 * 272 + nt2 * 16 * 2);
                #pragma unroll
                for (int mt = 0; mt < 2; mt++)
                    #pragma unroll
                    for (int nt = 0; nt < 8; nt++)
                        mma16816(acc[mt][nt], a[mt], &b[nt >> 1][(nt & 1) * 2]);
            }
        }
    };

    ldchunk(0, 0); CP_COMMIT();
    #pragma unroll 1
    for (int it = 0; it < 8; it++) {
        CP_WAIT0();
        __syncthreads();
        if (it + 1 < 8) { ldchunk(it + 1, (it + 1) & 1); CP_COMMIT(); }
        compute(it & 1);
    }

    #pragma unroll
    for (int mt = 0; mt < 2; mt++) {
        #pragma unroll
        for (int hf = 0; hf < 2; hf++) {
            const int m = m0 + warp_m + mt * 16 + (lane >> 2) + hf * 8;
            float rv = 0.f;
            if (epi == 5) rv = 1.0f / den[m];
            #pragma unroll
            for (int nt = 0; nt < 8; nt++) {
                const int n = n0 + warp_n + nt * 8 + (lane & 3) * 2;
                float v0 = acc[mt][nt][hf * 2 + 0];
                float v1 = acc[mt][nt][hf * 2 + 1];
                if (epi == 5) {
                    v0 = v0 * rv + bias[n];
                    v1 = v1 * rv + bias[n + 1];
                }
                if (Cf)
                    *(float2*)&Cf[(long)m * 256 + n] = make_float2(v0, v1);
                if (Ch) {
                    unsigned hp, lp;
                    packHL(v0, v1, hp, lp);
                    *(unsigned*)&Ch[(long)m * 256 + n] = hp;
                    *(unsigned*)&Cl[(long)m * 256 + n] = lp;
                }
            }
        }
    }
}

// ===========================================================================
// Elementwise kernels
// ===========================================================================
__global__ void clear_kernel() {
    if (threadIdx.x < BATCH)
        ((unsigned*)(g_f + F_KMAX))[threadIdx.x] = 0u;
}

__global__ __launch_bounds__(256)
void conv4(const float* __restrict__ in0, const float* __restrict__ in1,
           __nv_bfloat16* __restrict__ outBase, long stride, long n4) {
    const float* in = (blockIdx.z == 0) ? in0 : in1;
    __nv_bfloat16* h = outBase + (long)blockIdx.z * 2 * stride;
    __nv_bfloat16* l = h + stride;
    long i = (long)blockIdx.x * 256 + threadIdx.x;
    if (i < n4) {
        float4 x = ((const float4*)in)[i];
        float xs[4] = {x.x, x.y, x.z, x.w};
        unsigned short hh[4], ll[4];
        #pragma unroll
        for (int j = 0; j < 4; j++) {
            __nv_bfloat16 hi = __float2bfloat16(xs[j]);
            hh[j] = __bfloat16_as_ushort(hi);
            ll[j] = __bfloat16_as_ushort(__float2bfloat16(xs[j] - __bfloat162float(hi)));
        }
        ((uint2*)h)[i] = make_uint2((unsigned)hh[0] | ((unsigned)hh[1] << 16),
                                    (unsigned)hh[2] | ((unsigned)hh[3] << 16));
        ((uint2*)l)[i] = make_uint2((unsigned)ll[0] | ((unsigned)ll[1] << 16),
                                    (unsigned)ll[2] | ((unsigned)ll[3] << 16));
    }
}

__global__ __launch_bounds__(256)
void tconvW(const float* __restrict__ w0, const float* __restrict__ w1) {
    __shared__ float t[32][33];
    const int zz = blockIdx.z;
    const float* in = (zz == 0) ? w0 : w1;
    __nv_bfloat16* oh = g_b + ((zz == 0) ? B_WQTH : B_WKTH);
    __nv_bfloat16* ol = g_b + ((zz == 0) ? B_WQTL : B_WKTL);
    const int r0 = blockIdx.x * 32, c0 = blockIdx.y * 32;
    const int tx = threadIdx.x, ty = threadIdx.y;
    #pragma unroll
    for (int d = 0; d < 4; d++)
        t[ty + 8 * d][tx] = in[(long)(r0 + ty + 8 * d) * 256 + c0 + tx];
    __syncthreads();
    #pragma unroll
    for (int d = 0; d < 4; d++) {
        const int cc = c0 + ty + 8 * d;
        float x = t[tx][ty + 8 * d];
        __nv_bfloat16 hi = __float2bfloat16(x);
        long o = (long)cc * 256 + r0 + tx;
        oh[o] = hi;
        ol[o] = __float2bfloat16(x - __bfloat162float(hi));
    }
}

// bias2[d] = sum_j bv[j] * Wo[j][d] + bo[d]
__global__ __launch_bounds__(256)
void bias2_kernel(const float* __restrict__ bv, const float* __restrict__ Wo,
                  const float* __restrict__ bo) {
    const int d = threadIdx.x;
    float s = bo[d];
    for (int j = 0; j < 256; j++)
        s += bv[j] * Wo[(long)j * 256 + d];
    g_f[F_BIAS2 + d] = s;
}

// kvsW reduce: 8 split-K partials -> row-major hi/lo
__global__ __launch_bounds__(256)
void kvsured() {
    const int b = blockIdx.y, m = blockIdx.x, c = threadIdx.x;
    const float* p = g_f + F_PART + (long)b * 8 * SZW + (long)m * 256 + c;
    float s = 0.f;
    #pragma unroll
    for (int spl = 0; spl < 8; spl++)
        s += p[(long)spl * SZW];
    __nv_bfloat16 hi = __float2bfloat16(s);
    const long o = (long)b * SZW + (long)m * 256 + c;
    g_b[B_KVSWH + o] = hi;
    g_b[B_KVSWL + o] = __float2bfloat16(s - __bfloat162float(hi));
}

__global__ __launch_bounds__(256) void kp_kernel() {
    const int row = blockIdx.x;
    const int b   = row >> 11;
    const int t   = threadIdx.x;
    const long base = (long)row * MFEAT;
    const float x = __bfloat162float(g_b[B_KSH + base + t])
                  + __bfloat162float(g_b[B_KSL + base + t]);
    const float xp = g_f[F_XK + base + t];
    __shared__ float sm8[8];
    const float diag = 0.5f * blockSum256(x * x, sm8);
    const float mx = ord_dec(((const unsigned*)(g_f + F_KMAX))[b]);
    const float kp = 0.0625f * (expf(xp - diag - mx) + 1e-6f);
    __nv_bfloat16 hi = __float2bfloat16(kp);
    g_b[B_KPH + base + t] = hi;
    g_b[B_KPL + base + t] = __float2bfloat16(kp - __bfloat162float(hi));
}

__global__ __launch_bounds__(256) void ksump_kernel() {
    const int b = blockIdx.y, chunk = blockIdx.x, m = threadIdx.x;
    const long baseh = B_KPH + (long)b * L_SEQ * MFEAT;
    const long basel = B_KPL + (long)b * L_SEQ * MFEAT;
    float s = 0.f;
    const int r0 = chunk * 32;
    #pragma unroll 4
    for (int r = 0; r < 32; r++) {
        const long o = (long)(r0 + r) * MFEAT + m;
        s += __bfloat162float(g_b[baseh + o]) + __bfloat162float(g_b[basel + o]);
    }
    g_f[F_KSUMP + ((long)b * KCH + chunk) * MFEAT + m] = s;
}

__global__ __launch_bounds__(256) void ksumfold_kernel() {
    const int b = blockIdx.x, t = threadIdx.x;
    float s = 0.f;
    #pragma unroll
    for (int c = 0; c < KCH; c++)
        s += g_f[F_KSUMP + ((long)b * KCH + c) * MFEAT + t];
    g_f[F_KSUM + (long)b * MFEAT + t] = s;
}

__global__ __launch_bounds__(256) void qpden_kernel() {
    const int row = blockIdx.x;
    const int b   = row >> 11;
    const int t   = threadIdx.x;
    const long base = (long)row * MFEAT;
    const float x = __bfloat162float(g_b[B_QSH + base + t])
                  + __bfloat162float(g_b[B_QSL + base + t]);
    const float xp = g_f[F_XQ + base + t];
    __shared__ float sm8[8];
    const float diag = 0.5f * blockSum256(x * x, sm8);
    const float mx   = blockMax256(xp, sm8);
    const float qp = 0.0625f * (expf(xp - diag - mx) + 1e-6f);
    __nv_bfloat16 hi = __float2bfloat16(qp);
    g_b[B_QPH + base + t] = hi;
    g_b[B_QPL + base + t] = __float2bfloat16(qp - __bfloat162float(hi));
    const float ks = g_f[F_KSUM + (long)b * MFEAT + t];
    const float den = blockSum256(qp * ks, sm8);
    if (t == 0) g_f[F_DEN + row] = den;
}

// ===========================================================================
// launch — fork/join across two streams
// ===========================================================================
extern "C" void kernel_launch(void* const* d_in, const int* in_sizes, int n_in,
                              void* d_out, int out_size)
{
    const float* query = (const float*)d_in[0];
    const float* key   = (const float*)d_in[1];
    const float* value = (const float*)d_in[2];
    const float* Wq = (const float*)d_in[4];
    const float* bq = (const float*)d_in[5];
    const float* Wk = (const float*)d_in[6];
    const float* bk = (const float*)d_in[7];
    const float* Wv = (const float*)d_in[8];
    const float* bv = (const float*)d_in[9];
    const float* Wo = (const float*)d_in[10];
    const float* bo = (const float*)d_in[11];
    const float* proj = (const float*)d_in[12];
    const float* pos  = (const float*)d_in[13];
    float* out = (float*)d_out;

    void* fp = nullptr; cudaGetSymbolAddress(&fp, g_f);
    void* bp = nullptr; cudaGetSymbolAddress(&bp, g_b);
    float* F = (float*)fp;
    __nv_bfloat16* Bp = (__nv_bfloat16*)bp;

    static cudaStream_t s2 = nullptr;
    static cudaEvent_t evF, evW, evW2, evV, evVW, evK, evD;
    if (!s2) {
        cudaFuncSetAttribute(mma_nt, cudaFuncAttributeMaxDynamicSharedMemorySize, 81920);
        cudaFuncSetAttribute(mma_tn, cudaFuncAttributeMaxDynamicSharedMemorySize, 69632);
        cudaFuncSetAttribute(mma_nn, cudaFuncAttributeMaxDynamicSharedMemorySize, 75776);
        cudaStreamCreateWithFlags(&s2, cudaStreamNonBlocking);
        cudaEventCreateWithFlags(&evF,  cudaEventDisableTiming);
        cudaEventCreateWithFlags(&evW,  cudaEventDisableTiming);
        cudaEventCreateWithFlags(&evW2, cudaEventDisableTiming);
        cudaEventCreateWithFlags(&evV,  cudaEventDisableTiming);
        cudaEventCreateWithFlags(&evVW, cudaEventDisableTiming);
        cudaEventCreateWithFlags(&evK,  cudaEventDisableTiming);
        cudaEventCreateWithFlags(&evD,  cudaEventDisableTiming);
    }
    const int SM_NT = 81920, SM_TN = 69632, SM_NN = 75776;
    dim3 tb(32, 8);

    // ---- main stream first node, then fork s2 off it ----
    clear_kernel<<<1, 32>>>();
    cudaEventRecord(evF, 0);

    // ---- stream 2: weight chain ----
    cudaStreamWaitEvent(s2, evF, 0);
    tconvW<<<dim3(8, 8, 2), tb, 0, s2>>>(Wq, Wk);
    cudaEventRecord(evW, s2);
    conv4<<<dim3(64, 1, 2), 256, 0, s2>>>(Wv, Wo, Bp + B_WVINH, SZW, SZW / 4);
    // W2 = Wv @ Wo  (NN, tiny — overlapped, off critical path)
    mma_nn<<<dim3(2, 2, 1), 256, SM_NN, s2>>>(
        Bp + B_WVINH, Bp + B_WVINL, Bp + B_WOINH, Bp + B_WOINL,
        nullptr, Bp + B_W2H, Bp + B_W2L,
        nullptr, nullptr, 0, 0, 0, 0, 0);
    bias2_kernel<<<1, 256, 0, s2>>>(bv, Wo, bo);
    cudaEventRecord(evW2, s2);

    // ---- main stream: input conversions ----
    conv4<<<dim3((unsigned)(SZB / 1024), 1, 2), 256>>>(query, key, Bp + B_QINH, SZB, SZB / 4);
    conv4<<<dim3((unsigned)(SZB / 1024), 1, 1), 256>>>(value, value, Bp + B_VINH, SZB, SZB / 4);
    cudaEventRecord(evV, 0);
    conv4<<<dim3(64, 1, 1), 256>>>(proj, proj, Bp + B_PRJH, SZW, SZW / 4);

    // ---- stream 2: valueW2 = value @ W2  (big NN, fully overlapped) ----
    cudaStreamWaitEvent(s2, evV, 0);
    mma_nn<<<dim3(2, 64, 1), 256, SM_NN, s2>>>(
        Bp + B_VINH, Bp + B_VINL, Bp + B_W2H, Bp + B_W2L,
        nullptr, Bp + B_VW2H, Bp + B_VW2L,
        nullptr, nullptr, 0, 0, 0, 0, 0);
    cudaEventRecord(evVW, s2);

    // ---- main: q/k projections (needs WQT/WKT) ----
    cudaStreamWaitEvent(0, evW, 0);
    mma_nt<<<dim3(2, 64, 2), 256, SM_NT>>>(
        Bp + B_QINH, Bp + B_QINL, Bp + B_WQTH, Bp + B_WQTL,
        nullptr, Bp + B_QSH, Bp + B_QSL,
        bq, bk, pos,
        2 * SZB, 2 * SZW, 2 * SZB, 2, -1);

    // xq/xk: z=0 -> XQ, z=1 -> XK (+per-batch max)
    mma_nt<<<dim3(2, 64, 2), 256, SM_NT>>>(
        Bp + B_QSH, Bp + B_QSL, Bp + B_PRJH, Bp + B_PRJL,
        F + F_XQ, nullptr, nullptr,
        nullptr, nullptr, nullptr,
        2 * SZB, 0, SZB, 0, 1);

    kp_kernel<<<NROWS, 256>>>();
    cudaEventRecord(evK, 0);

    // ---- stream 2: ksum + qpden (overlap with kvsW GEMM) ----
    cudaStreamWaitEvent(s2, evK, 0);
    ksump_kernel<<<dim3(KCH, BATCH), 256, 0, s2>>>();
    ksumfold_kernel<<<BATCH, 256, 0, s2>>>();
    qpden_kernel<<<NROWS, 256, 0, s2>>>();
    cudaEventRecord(evD, s2);

    // ---- main: kvsW = kp^T @ valueW2  (TN, split-K 8) ----
    cudaStreamWaitEvent(0, evVW, 0);
    mma_tn<<<dim3(2, 2, 32), 256, SM_TN>>>(
        Bp + B_KPH, Bp + B_KPL, Bp + B_VW2H, Bp + B_VW2L,
        F + F_PART,
        (long)L_SEQ * MFEAT, (long)256 * MFEAT,
        (long)L_SEQ * 256,  (long)256 * 256,
        (long)8 * SZW, SZW);
    kvsured<<<dim3(256, BATCH), 256>>>();

    // ---- main: out = (qp @ kvsW)/den + (bvWo + bo)  (NN, batched) ----
    cudaStreamWaitEvent(0, evD, 0);
    cudaStreamWaitEvent(0, evW2, 0);
    mma_nn<<<dim3(2, 16, 4), 256, SM_NN>>>(
        Bp + B_QPH, Bp + B_QPL, Bp + B_KVSWH, Bp + B_KVSWL,
        out, nullptr, nullptr,
        F + F_BIAS2, F + F_DEN,
        (long)L_SEQ * 256, SZW, (long)L_SEQ * 256, L_SEQ, 5);
}

// round 17
// speedup vs baseline: 1.1382x; 1.0736x over previous
#include <cuda_runtime.h>
#include <cuda_bf16.h>
#include <math.h>
#include <stdint.h>

#define L_SEQ   2048
#define DMODEL  256
#define BATCH   4
#define MFEAT   256
#define NROWS   8192
#define TN_SPLIT 16
#define TN_CHPP  4        // (2048/TN_SPLIT)/32 chunks per pass

// ===========================================================================
// Scratch
// ===========================================================================
static constexpr long SZB = (long)NROWS * DMODEL;   // 2,097,152
static constexpr long SZW = 65536;
static constexpr int  KCH = 64;

// f32 scratch
static constexpr long F_XQ    = 0;
static constexpr long F_XK    = F_XQ + SZB;
static constexpr long F_PART  = F_XK + SZB;                 // 64 * SZW
static constexpr long F_DEN   = F_PART + (long)BATCH * TN_SPLIT * SZW;
static constexpr long F_KSUMP = F_DEN + NROWS;
static constexpr long F_KSUM  = F_KSUMP + (long)BATCH * KCH * MFEAT;
static constexpr long F_BIAS2 = F_KSUM + (long)BATCH * MFEAT;   // bvWo + bo
static constexpr long F_KMAX  = F_BIAS2 + MFEAT;
static constexpr long F_TOTAL = F_KMAX + 16;
__device__ float g_f[F_TOTAL];

// bf16 scratch
static constexpr long B_QINH = 0;
static constexpr long B_QINL = B_QINH + SZB;
static constexpr long B_KINH = B_QINL + SZB;
static constexpr long B_KINL = B_KINH + SZB;
static constexpr long B_VINH = B_KINL + SZB;
static constexpr long B_VINL = B_VINH + SZB;
static constexpr long B_VW2H = B_VINL + SZB;    // value @ W2 (bf16 hi/lo)
static constexpr long B_VW2L = B_VW2H + SZB;
static constexpr long B_QSH  = B_VW2L + SZB;
static constexpr long B_QSL  = B_QSH + SZB;
static constexpr long B_KSH  = B_QSL + SZB;
static constexpr long B_KSL  = B_KSH + SZB;
static constexpr long B_QPH  = B_KSL + SZB;
static constexpr long B_QPL  = B_QPH + SZB;
static constexpr long B_KPH  = B_QPL + SZB;
static constexpr long B_KPL  = B_KPH + SZB;
static constexpr long B_WQTH = B_KPL + SZB;
static constexpr long B_WQTL = B_WQTH + SZW;
static constexpr long B_WKTH = B_WQTL + SZW;
static constexpr long B_WKTL = B_WKTH + SZW;
static constexpr long B_PRJH = B_WKTL + SZW;
static constexpr long B_PRJL = B_PRJH + SZW;
static constexpr long B_WVINH = B_PRJL + SZW;   // conv4 z=0
static constexpr long B_WVINL = B_WVINH + SZW;
static constexpr long B_WOINH = B_WVINL + SZW;  // conv4 z=1
static constexpr long B_WOINL = B_WOINH + SZW;
static constexpr long B_W2H  = B_WOINL + SZW;
static constexpr long B_W2L  = B_W2H + SZW;
static constexpr long B_KVSWH = B_W2L + SZW;    // 4*SZW (kvsW = kp^T @ valueW2)
static constexpr long B_KVSWL = B_KVSWH + 4 * SZW;
static constexpr long B_TOTAL = B_KVSWL + 4 * SZW;
__device__ __nv_bfloat16 g_b[B_TOTAL];

// ===========================================================================
// Helpers
// ===========================================================================
__device__ __forceinline__ uint32_t smem_u32(const void* p) {
    uint32_t a;
    asm("{ .reg .u64 t; cvta.to.shared.u64 t, %1; cvt.u32.u64 %0, t; }"
        : "=r"(a) : "l"(p));
    return a;
}
__device__ __forceinline__ void cp16(uint32_t dst, const void* src) {
    asm volatile("cp.async.cg.shared.global [%0], [%1], 16;"
                 :: "r"(dst), "l"(src) : "memory");
}
#define CP_COMMIT()  asm volatile("cp.async.commit_group;" ::: "memory")
#define CP_WAIT0()   asm volatile("cp.async.wait_group 0;" ::: "memory")

__device__ __forceinline__ void ldsm_x4(uint32_t& r0, uint32_t& r1,
                                        uint32_t& r2, uint32_t& r3, uint32_t addr) {
    asm volatile("ldmatrix.sync.aligned.m8n8.x4.shared.b16 {%0,%1,%2,%3}, [%4];"
                 : "=r"(r0), "=r"(r1), "=r"(r2), "=r"(r3) : "r"(addr));
}
__device__ __forceinline__ void ldsm_x4_t(uint32_t& r0, uint32_t& r1,
                                          uint32_t& r2, uint32_t& r3, uint32_t addr) {
    asm volatile("ldmatrix.sync.aligned.m8n8.x4.trans.shared.b16 {%0,%1,%2,%3}, [%4];"
                 : "=r"(r0), "=r"(r1), "=r"(r2), "=r"(r3) : "r"(addr));
}
__device__ __forceinline__ void mma16816(float* d, const uint32_t* a, const uint32_t* b) {
    asm volatile("mma.sync.aligned.m16n8k16.row.col.f32.bf16.bf16.f32 "
                 "{%0,%1,%2,%3}, {%4,%5,%6,%7}, {%8,%9}, {%0,%1,%2,%3};"
                 : "+f"(d[0]), "+f"(d[1]), "+f"(d[2]), "+f"(d[3])
                 : "r"(a[0]), "r"(a[1]), "r"(a[2]), "r"(a[3]), "r"(b[0]), "r"(b[1]));
}
__device__ __forceinline__ unsigned ord_enc(float f) {
    unsigned u = __float_as_uint(f);
    return (u & 0x80000000u) ? ~u : (u | 0x80000000u);
}
__device__ __forceinline__ float ord_dec(unsigned u) {
    return __uint_as_float((u & 0x80000000u) ? (u & 0x7fffffffu) : ~u);
}
__device__ __forceinline__ float blockSum256(float v, float* sm8) {
    #pragma unroll
    for (int o = 16; o; o >>= 1) v += __shfl_xor_sync(0xffffffffu, v, o);
    if ((threadIdx.x & 31) == 0) sm8[threadIdx.x >> 5] = v;
    __syncthreads();
    float s = 0.f;
    #pragma unroll
    for (int i = 0; i < 8; i++) s += sm8[i];
    __syncthreads();
    return s;
}
__device__ __forceinline__ float blockMax256(float v, float* sm8) {
    #pragma unroll
    for (int o = 16; o; o >>= 1) v = fmaxf(v, __shfl_xor_sync(0xffffffffu, v, o));
    if ((threadIdx.x & 31) == 0) sm8[threadIdx.x >> 5] = v;
    __syncthreads();
    float s = sm8[0];
    #pragma unroll
    for (int i = 1; i < 8; i++) s = fmaxf(s, sm8[i]);
    __syncthreads();
    return s;
}
__device__ __forceinline__ void packHL(float v0, float v1,
                                       unsigned& hp, unsigned& lp) {
    __nv_bfloat16 h0 = __float2bfloat16(v0);
    __nv_bfloat16 h1 = __float2bfloat16(v1);
    float l0 = v0 - __bfloat162float(h0);
    float l1 = v1 - __bfloat162float(h1);
    hp = ((unsigned)__bfloat16_as_ushort(h1) << 16) | __bfloat16_as_ushort(h0);
    lp = ((unsigned)__bfloat16_as_ushort(__float2bfloat16(l1)) << 16)
       | __bfloat16_as_ushort(__float2bfloat16(l0));
}

// ===========================================================================
// NT GEMM (bf16 3-pass, verified): 256 thr, 8 warps (4Mx2N), K=256.
//   epiMode: 0 none, 2 +bias+rotary+0.25
//   domaxZ: if z == domaxZ, atomicMax raw acc into g_f[F_KMAX + m0>>11]
// Stage (stride 40960): Ah@0 Al@10240 Bh@20480 Bl@30720 (80B rows)
// ===========================================================================
__global__ __launch_bounds__(256, 2)
void mma_nt(const __nv_bfloat16* __restrict__ Ah, const __nv_bfloat16* __restrict__ Al,
            const __nv_bfloat16* __restrict__ Bh, const __nv_bfloat16* __restrict__ Bl,
            float* __restrict__ Cf, __nv_bfloat16* __restrict__ Ch,
            __nv_bfloat16* __restrict__ Cl,
            const float* __restrict__ bias0, const float* __restrict__ bias1,
            const float* __restrict__ pos,
            long sAb, long sBb, long sCb,
            int epiMode, int domaxZ)
{
    extern __shared__ __align__(16) char smemBuf[];

    const int tid  = threadIdx.x;
    const int wid  = tid >> 5;
    const int lane = tid & 31;
    const int warp_m = (wid >> 1) * 32;
    const int warp_n = (wid & 1) * 64;

    const int z = blockIdx.z;
    const float* bias = (z == 0) ? bias0 : bias1;
    if (Cf) Cf += (long)z * sCb;
    if (Ch) { Ch += (long)z * sCb; Cl += (long)z * sCb; }

    const int m0 = blockIdx.y * 128;
    const int n0 = blockIdx.x * 128;
    const uint32_t sbase = smem_u32(smemBuf);

    const int lrow = tid >> 1;
    const int lcol = (tid & 1) * 16;
    const long zA = (long)z * sAb;
    const long zB = (long)z * sBb;
    const __nv_bfloat16* aH = Ah + zA + (long)(m0 + lrow) * 256 + lcol;
    const __nv_bfloat16* aL = Al + zA + (long)(m0 + lrow) * 256 + lcol;
    const __nv_bfloat16* bH = Bh + zB + (long)(n0 + lrow) * 256 + lcol;
    const __nv_bfloat16* bL = Bl + zB + (long)(n0 + lrow) * 256 + lcol;
    const uint32_t dstA = sbase + lrow * 80 + (tid & 1) * 32;
    const uint32_t dstB = dstA + 20480;

    auto ldchunk = [&](int ck, int slot) {
        const int kk = ck * 32;
        const uint32_t so = slot * 40960;
        cp16(dstA + so,              aH + kk);
        cp16(dstA + so + 16,         aH + kk + 8);
        cp16(dstA + so + 10240,      aL + kk);
        cp16(dstA + so + 10240 + 16, aL + kk + 8);
        cp16(dstB + so,              bH + kk);
        cp16(dstB + so + 16,         bH + kk + 8);
        cp16(dstB + so + 10240,      bL + kk);
        cp16(dstB + so + 10240 + 16, bL + kk + 8);
    };

    const uint32_t aoffl = (warp_m + (lane & 15)) * 80 + (lane >> 4) * 16;
    const uint32_t boffl = (warp_n + (lane & 7) + ((lane >> 4) & 1) * 8) * 80
                         + ((lane >> 3) & 1) * 16;

    float acc[2][8][4] = {};

    auto compute = [&](int slot) {
        const uint32_t base = sbase + slot * 40960;
        #pragma unroll
        for (int pass = 0; pass < 3; pass++) {
            const uint32_t bA = base + ((pass == 2) ? 10240u : 0u);
            const uint32_t bB = base + 20480u + ((pass == 1) ? 10240u : 0u);
            #pragma unroll
            for (int k16 = 0; k16 < 2; k16++) {
                uint32_t a[2][4];
                #pragma unroll
                for (int mt = 0; mt < 2; mt++)
                    ldsm_x4(a[mt][0], a[mt][1], a[mt][2], a[mt][3],
                            bA + aoffl + mt * 16 * 80 + k16 * 32);
                uint32_t b[4][4];
                #pragma unroll
                for (int nt2 = 0; nt2 < 4; nt2++)
                    ldsm_x4(b[nt2][0], b[nt2][1], b[nt2][2], b[nt2][3],
                            bB + boffl + nt2 * 16 * 80 + k16 * 32);
                #pragma unroll
                for (int mt = 0; mt < 2; mt++)
                    #pragma unroll
                    for (int nt = 0; nt < 8; nt++)
                        mma16816(acc[mt][nt], a[mt], &b[nt >> 1][(nt & 1) * 2]);
            }
        }
    };

    ldchunk(0, 0); CP_COMMIT();
    #pragma unroll 1
    for (int it = 0; it < 8; it++) {
        CP_WAIT0();
        __syncthreads();
        if (it + 1 < 8) { ldchunk(it + 1, (it + 1) & 1); CP_COMMIT(); }
        compute(it & 1);
    }

    if (z == domaxZ) {
        float mx = -3.402823466e38f;
        #pragma unroll
        for (int mt = 0; mt < 2; mt++)
            #pragma unroll
            for (int nt = 0; nt < 8; nt++)
                #pragma unroll
                for (int q = 0; q < 4; q++)
                    mx = fmaxf(mx, acc[mt][nt][q]);
        __syncthreads();
        mx = blockMax256(mx, (float*)smemBuf);
        if (tid == 0)
            atomicMax((unsigned*)(g_f + F_KMAX) + (m0 >> 11), ord_enc(mx));
    }

    #pragma unroll
    for (int mt = 0; mt < 2; mt++) {
        #pragma unroll
        for (int hf = 0; hf < 2; hf++) {
            const int m = m0 + warp_m + mt * 16 + (lane >> 2) + hf * 8;
            const int l = m & (L_SEQ - 1);
            #pragma unroll
            for (int nt = 0; nt < 8; nt++) {
                const int n = n0 + warp_n + nt * 8 + (lane & 3) * 2;
                float v0 = acc[mt][nt][hf * 2 + 0];
                float v1 = acc[mt][nt][hf * 2 + 1];
                if (epiMode == 2) {
                    v0 += bias[n]; v1 += bias[n + 1];
                    const float sn = pos[(long)l * DMODEL + n];
                    const float cs = pos[(long)l * DMODEL + n + 1];
                    const float q0 = v0 * cs - v1 * sn;
                    const float q1 = v1 * cs + v0 * sn;
                    v0 = q0 * 0.25f; v1 = q1 * 0.25f;
                }
                if (Cf)
                    *(float2*)&Cf[(long)m * 256 + n] = make_float2(v0, v1);
                if (Ch) {
                    unsigned hp, lp;
                    packHL(v0, v1, hp, lp);
                    *(unsigned*)&Ch[(long)m * 256 + n] = hp;
                    *(unsigned*)&Cl[(long)m * 256 + n] = lp;
                }
            }
        }
    }
}

// ===========================================================================
// TN GEMM (bf16 3-pass): A [K,M], B [K,N], ldmatrix .trans.
//   Split-K 16: z = bz*16+sp, 128 K-rows/split; 12 chunk-iterations; f32 out.
// Stage (stride 34816): Ah@0 Al@8704 Bh@17408 Bl@26112 (272B rows)
// ===========================================================================
__global__ __launch_bounds__(256, 2)
void mma_tn(const __nv_bfloat16* __restrict__ Ah, const __nv_bfloat16* __restrict__ Al,
            const __nv_bfloat16* __restrict__ Bh, const __nv_bfloat16* __restrict__ Bl,
            float* __restrict__ Cf,
            long sAb, long sAs, long sBb, long sBs, long sCb, long sCs)
{
    extern __shared__ __align__(16) char smemBuf[];

    const int tid  = threadIdx.x;
    const int wid  = tid >> 5;
    const int lane = tid & 31;
    const int warp_m = (wid >> 1) * 32;
    const int warp_n = (wid & 1) * 64;

    const int z  = blockIdx.z;
    const int bz = z >> 4, sp = z & 15;
    const long aoff = (long)bz * sAb + (long)sp * sAs;
    const long boff = (long)bz * sBb + (long)sp * sBs;
    Cf += (long)bz * sCb + (long)sp * sCs;

    const int m0 = blockIdx.y * 128;
    const int n0 = blockIdx.x * 128;
    const uint32_t sbase = smem_u32(smemBuf);

    const int lrow = tid >> 3;
    const int lcol = (tid & 7) * 16;
    const __nv_bfloat16* aH = Ah + aoff + (long)lrow * 256 + m0 + lcol;
    const __nv_bfloat16* aL = Al + aoff + (long)lrow * 256 + m0 + lcol;
    const __nv_bfloat16* bH = Bh + boff + (long)lrow * 256 + n0 + lcol;
    const __nv_bfloat16* bL = Bl + boff + (long)lrow * 256 + n0 + lcol;
    const uint32_t dstA = sbase + lrow * 272 + (tid & 7) * 32;
    const uint32_t dstB = dstA + 17408;

    auto ldchunk = [&](int ck, int slot) {
        const int pass = ck >> 2;          // ck / TN_CHPP
        const long kk = (long)(ck & 3) * 32 * 256;
        const __nv_bfloat16* Ap = (pass == 2) ? aL : aH;
        const __nv_bfloat16* Bq = (pass == 1) ? bL : bH;
        const uint32_t so = slot * 34816;
        cp16(dstA + so,      Ap + kk);
        cp16(dstA + so + 16, Ap + kk + 8);
        cp16(dstB + so,      Bq + kk);
        cp16(dstB + so + 16, Bq + kk + 8);
    };

    const uint32_t aoffl = ((lane & 7) + ((lane >> 4) & 1) * 8) * 272
                         + (warp_m + ((lane >> 3) & 1) * 8) * 2;
    const uint32_t boffl = ((lane & 7) + ((lane >> 3) & 1) * 8) * 272
                         + (warp_n + ((lane >> 4) & 1) * 8) * 2;

    float acc[2][8][4] = {};

    auto compute = [&](int slot) {
        const uint32_t bA = sbase + slot * 34816;
        const uint32_t bB = bA + 17408;
        #pragma unroll
        for (int k16 = 0; k16 < 2; k16++) {
            uint32_t a[2][4];
            #pragma unroll
            for (int mt = 0; mt < 2; mt++)
                ldsm_x4_t(a[mt][0], a[mt][1], a[mt][2], a[mt][3],
                          bA + aoffl + k16 * 16 * 272 + mt * 16 * 2);
            uint32_t b[4][4];
            #pragma unroll
            for (int nt2 = 0; nt2 < 4; nt2++)
                ldsm_x4_t(b[nt2][0], b[nt2][1], b[nt2][2], b[nt2][3],
                          bB + boffl + k16 * 16 * 272 + nt2 * 16 * 2);
            #pragma unroll
            for (int mt = 0; mt < 2; mt++)
                #pragma unroll
                for (int nt = 0; nt < 8; nt++)
                    mma16816(acc[mt][nt], a[mt], &b[nt >> 1][(nt & 1) * 2]);
        }
    };

    const int NCH = 3 * TN_CHPP;   // 12
    ldchunk(0, 0); CP_COMMIT();
    #pragma unroll 1
    for (int it = 0; it < NCH; it++) {
        CP_WAIT0();
        __syncthreads();
        if (it + 1 < NCH) { ldchunk(it + 1, (it + 1) & 1); CP_COMMIT(); }
        compute(it & 1);
    }

    #pragma unroll
    for (int mt = 0; mt < 2; mt++)
        #pragma unroll
        for (int hf = 0; hf < 2; hf++) {
            const int m = m0 + warp_m + mt * 16 + (lane >> 2) + hf * 8;
            #pragma unroll
            for (int nt = 0; nt < 8; nt++) {
                const int n = n0 + warp_n + nt * 8 + (lane & 3) * 2;
                *(float2*)&Cf[(long)m * 256 + n] =
                    make_float2(acc[mt][nt][hf * 2], acc[mt][nt][hf * 2 + 1]);
            }
        }
}

// ===========================================================================
// NN GEMM (bf16 3-pass): A [M,K=256] row-major, B [K=256,N] row-major.
//   epi: 0 none, 5 = /den[m] + bias[n]
// Stage (stride 37888): Ah@0 Al@10240 Bh@20480 Bl@29184
// ===========================================================================
__global__ __launch_bounds__(256, 2)
void mma_nn(const __nv_bfloat16* __restrict__ Ah, const __nv_bfloat16* __restrict__ Al,
            const __nv_bfloat16* __restrict__ Bh, const __nv_bfloat16* __restrict__ Bl,
            float* __restrict__ Cf, __nv_bfloat16* __restrict__ Ch,
            __nv_bfloat16* __restrict__ Cl,
            const float* __restrict__ bias, const float* __restrict__ den,
            long sAb, long sBb, long sCb, long sDen, int epi)
{
    extern __shared__ __align__(16) char smemBuf[];   // 2 x 37888

    const int tid  = threadIdx.x;
    const int wid  = tid >> 5;
    const int lane = tid & 31;
    const int warp_m = (wid >> 1) * 32;
    const int warp_n = (wid & 1) * 64;

    const int z = blockIdx.z;
    Ah += (long)z * sAb; Al += (long)z * sAb;
    Bh += (long)z * sBb; Bl += (long)z * sBb;
    if (Cf) Cf += (long)z * sCb;
    if (Ch) { Ch += (long)z * sCb; Cl += (long)z * sCb; }
    if (epi == 5) den += (long)z * sDen;

    const int m0 = blockIdx.y * 128;
    const int n0 = blockIdx.x * 128;
    const uint32_t sbase = smem_u32(smemBuf);

    const int lrowA = tid >> 1;
    const __nv_bfloat16* aH = Ah + (long)(m0 + lrowA) * 256 + (tid & 1) * 16;
    const __nv_bfloat16* aL = Al + (long)(m0 + lrowA) * 256 + (tid & 1) * 16;
    const uint32_t dstA = sbase + lrowA * 80 + (tid & 1) * 32;
    const int lrowB = tid >> 3;
    const __nv_bfloat16* bH = Bh + (long)lrowB * 256 + n0 + (tid & 7) * 16;
    const __nv_bfloat16* bL = Bl + (long)lrowB * 256 + n0 + (tid & 7) * 16;
    const uint32_t dstB = sbase + 20480 + lrowB * 272 + (tid & 7) * 32;

    auto ldchunk = [&](int ck, int slot) {
        const int  kkA = ck * 32;
        const long kkB = (long)ck * 32 * 256;
        const uint32_t so = slot * 37888;
        cp16(dstA + so,              aH + kkA);
        cp16(dstA + so + 16,         aH + kkA + 8);
        cp16(dstA + so + 10240,      aL + kkA);
        cp16(dstA + so + 10240 + 16, aL + kkA + 8);
        cp16(dstB + so,             bH + kkB);
        cp16(dstB + so + 16,        bH + kkB + 8);
        cp16(dstB + so + 8704,      bL + kkB);
        cp16(dstB + so + 8704 + 16, bL + kkB + 8);
    };

    const uint32_t aoffl = (warp_m + (lane & 15)) * 80 + (lane >> 4) * 16;
    const uint32_t boffl = ((lane & 7) + ((lane >> 3) & 1) * 8) * 272
                         + (warp_n + ((lane >> 4) & 1) * 8) * 2;

    float acc[2][8][4] = {};

    auto compute = [&](int slot) {
        const uint32_t base = sbase + slot * 37888;
        #pragma unroll
        for (int pass = 0; pass < 3; pass++) {
            const uint32_t bA = base + ((pass == 2) ? 10240u : 0u);
            const uint32_t bB = base + 20480u + ((pass == 1) ? 8704u : 0u);
            #pragma unroll
            for (int k16 = 0; k16 < 2; k16++) {
                uint32_t a[2][4];
                #pragma unroll
                for (int mt = 0; mt < 2; mt++)
                    ldsm_x4(a[mt][0], a[mt][1], a[mt][2], a[mt][3],
                            bA + aoffl + mt * 16 * 80 + k16 * 32);
                uint32_t b[4][4];
                #pragma unroll
                for (int nt2 = 0; nt2 < 4; nt2++)
                    ldsm_x4_t(b[nt2][0], b[nt2][1], b[nt2][2], b[nt2][3],
                              bB + boffl + k16 * 16 * 272 + nt2 * 16 * 2);
                #pragma unroll
                for (int mt = 0; mt < 2; mt++)
                    #pragma unroll
                    for (int nt = 0; nt < 8; nt++)
                        mma16816(acc[mt][nt], a[mt], &b[nt >> 1][(nt & 1) * 2]);
            }
        }
    };

    ldchunk(0, 0); CP_COMMIT();
    #pragma unroll 1
    for (int it = 0; it < 8; it++) {
        CP_WAIT0();
        __syncthreads();
        if (it + 1 < 8) { ldchunk(it + 1, (it + 1) & 1); CP_COMMIT(); }
        compute(it & 1);
    }

    #pragma unroll
    for (int mt = 0; mt < 2; mt++) {
        #pragma unroll
        for (int hf = 0; hf < 2; hf++) {
            const int m = m0 + warp_m + mt * 16 + (lane >> 2) + hf * 8;
            float rv = 0.f;
            if (epi == 5) rv = 1.0f / den[m];
            #pragma unroll
            for (int nt = 0; nt < 8; nt++) {
                const int n = n0 + warp_n + nt * 8 + (lane & 3) * 2;
                float v0 = acc[mt][nt][hf * 2 + 0];
                float v1 = acc[mt][nt][hf * 2 + 1];
                if (epi == 5) {
                    v0 = v0 * rv + bias[n];
                    v1 = v1 * rv + bias[n + 1];
                }
                if (Cf)
                    *(float2*)&Cf[(long)m * 256 + n] = make_float2(v0, v1);
                if (Ch) {
                    unsigned hp, lp;
                    packHL(v0, v1, hp, lp);
                    *(unsigned*)&Ch[(long)m * 256 + n] = hp;
                    *(unsigned*)&Cl[(long)m * 256 + n] = lp;
                }
            }
        }
    }
}

// ===========================================================================
// Elementwise kernels
// ===========================================================================
__global__ void clear_kernel() {
    if (threadIdx.x < BATCH)
        ((unsigned*)(g_f + F_KMAX))[threadIdx.x] = 0u;
}

__global__ __launch_bounds__(256)
void conv4(const float* __restrict__ in0, const float* __restrict__ in1,
           __nv_bfloat16* __restrict__ outBase, long stride, long n4) {
    const float* in = (blockIdx.z == 0) ? in0 : in1;
    __nv_bfloat16* h = outBase + (long)blockIdx.z * 2 * stride;
    __nv_bfloat16* l = h + stride;
    long i = (long)blockIdx.x * 256 + threadIdx.x;
    if (i < n4) {
        float4 x = ((const float4*)in)[i];
        float xs[4] = {x.x, x.y, x.z, x.w};
        unsigned short hh[4], ll[4];
        #pragma unroll
        for (int j = 0; j < 4; j++) {
            __nv_bfloat16 hi = __float2bfloat16(xs[j]);
            hh[j] = __bfloat16_as_ushort(hi);
            ll[j] = __bfloat16_as_ushort(__float2bfloat16(xs[j] - __bfloat162float(hi)));
        }
        ((uint2*)h)[i] = make_uint2((unsigned)hh[0] | ((unsigned)hh[1] << 16),
                                    (unsigned)hh[2] | ((unsigned)hh[3] << 16));
        ((uint2*)l)[i] = make_uint2((unsigned)ll[0] | ((unsigned)ll[1] << 16),
                                    (unsigned)ll[2] | ((unsigned)ll[3] << 16));
    }
}

__global__ __launch_bounds__(256)
void tconvW(const float* __restrict__ w0, const float* __restrict__ w1) {
    __shared__ float t[32][33];
    const int zz = blockIdx.z;
    const float* in = (zz == 0) ? w0 : w1;
    __nv_bfloat16* oh = g_b + ((zz == 0) ? B_WQTH : B_WKTH);
    __nv_bfloat16* ol = g_b + ((zz == 0) ? B_WQTL : B_WKTL);
    const int r0 = blockIdx.x * 32, c0 = blockIdx.y * 32;
    const int tx = threadIdx.x, ty = threadIdx.y;
    #pragma unroll
    for (int d = 0; d < 4; d++)
        t[ty + 8 * d][tx] = in[(long)(r0 + ty + 8 * d) * 256 + c0 + tx];
    __syncthreads();
    #pragma unroll
    for (int d = 0; d < 4; d++) {
        const int cc = c0 + ty + 8 * d;
        float x = t[tx][ty + 8 * d];
        __nv_bfloat16 hi = __float2bfloat16(x);
        long o = (long)cc * 256 + r0 + tx;
        oh[o] = hi;
        ol[o] = __float2bfloat16(x - __bfloat162float(hi));
    }
}

// bias2[d] = sum_j bv[j] * Wo[j][d] + bo[d]
__global__ __launch_bounds__(256)
void bias2_kernel(const float* __restrict__ bv, const float* __restrict__ Wo,
                  const float* __restrict__ bo) {
    const int d = threadIdx.x;
    float s = bo[d];
    for (int j = 0; j < 256; j++)
        s += bv[j] * Wo[(long)j * 256 + d];
    g_f[F_BIAS2 + d] = s;
}

// kvsW reduce: 16 split-K partials -> row-major hi/lo
__global__ __launch_bounds__(256)
void kvsured() {
    const int b = blockIdx.y, m = blockIdx.x, c = threadIdx.x;
    const float* p = g_f + F_PART + (long)b * TN_SPLIT * SZW + (long)m * 256 + c;
    float s = 0.f;
    #pragma unroll
    for (int spl = 0; spl < TN_SPLIT; spl++)
        s += p[(long)spl * SZW];
    __nv_bfloat16 hi = __float2bfloat16(s);
    const long o = (long)b * SZW + (long)m * 256 + c;
    g_b[B_KVSWH + o] = hi;
    g_b[B_KVSWL + o] = __float2bfloat16(s - __bfloat162float(hi));
}

__global__ __launch_bounds__(256) void kp_kernel() {
    const int row = blockIdx.x;
    const int b   = row >> 11;
    const int t   = threadIdx.x;
    const long base = (long)row * MFEAT;
    const float x = __bfloat162float(g_b[B_KSH + base + t])
                  + __bfloat162float(g_b[B_KSL + base + t]);
    const float xp = g_f[F_XK + base + t];
    __shared__ float sm8[8];
    const float diag = 0.5f * blockSum256(x * x, sm8);
    const float mx = ord_dec(((const unsigned*)(g_f + F_KMAX))[b]);
    const float kp = 0.0625f * (expf(xp - diag - mx) + 1e-6f);
    __nv_bfloat16 hi = __float2bfloat16(kp);
    g_b[B_KPH + base + t] = hi;
    g_b[B_KPL + base + t] = __float2bfloat16(kp - __bfloat162float(hi));
}

__global__ __launch_bounds__(256) void ksump_kernel() {
    const int b = blockIdx.y, chunk = blockIdx.x, m = threadIdx.x;
    const long baseh = B_KPH + (long)b * L_SEQ * MFEAT;
    const long basel = B_KPL + (long)b * L_SEQ * MFEAT;
    float s = 0.f;
    const int r0 = chunk * 32;
    #pragma unroll 4
    for (int r = 0; r < 32; r++) {
        const long o = (long)(r0 + r) * MFEAT + m;
        s += __bfloat162float(g_b[baseh + o]) + __bfloat162float(g_b[basel + o]);
    }
    g_f[F_KSUMP + ((long)b * KCH + chunk) * MFEAT + m] = s;
}

__global__ __launch_bounds__(256) void ksumfold_kernel() {
    const int b = blockIdx.x, t = threadIdx.x;
    float s = 0.f;
    #pragma unroll
    for (int c = 0; c < KCH; c++)
        s += g_f[F_KSUMP + ((long)b * KCH + c) * MFEAT + t];
    g_f[F_KSUM + (long)b * MFEAT + t] = s;
}

__global__ __launch_bounds__(256) void qpden_kernel() {
    const int row = blockIdx.x;
    const int b   = row >> 11;
    const int t   = threadIdx.x;
    const long base = (long)row * MFEAT;
    const float x = __bfloat162float(g_b[B_QSH + base + t])
                  + __bfloat162float(g_b[B_QSL + base + t]);
    const float xp = g_f[F_XQ + base + t];
    __shared__ float sm8[8];
    const float diag = 0.5f * blockSum256(x * x, sm8);
    const float mx   = blockMax256(xp, sm8);
    const float qp = 0.0625f * (expf(xp - diag - mx) + 1e-6f);
    __nv_bfloat16 hi = __float2bfloat16(qp);
    g_b[B_QPH + base + t] = hi;
    g_b[B_QPL + base + t] = __float2bfloat16(qp - __bfloat162float(hi));
    const float ks = g_f[F_KSUM + (long)b * MFEAT + t];
    const float den = blockSum256(qp * ks, sm8);
    if (t == 0) g_f[F_DEN + row] = den;
}

// ===========================================================================
// launch — fork/join across two streams
// ===========================================================================
extern "C" void kernel_launch(void* const* d_in, const int* in_sizes, int n_in,
                              void* d_out, int out_size)
{
    const float* query = (const float*)d_in[0];
    const float* key   = (const float*)d_in[1];
    const float* value = (const float*)d_in[2];
    const float* Wq = (const float*)d_in[4];
    const float* bq = (const float*)d_in[5];
    const float* Wk = (const float*)d_in[6];
    const float* bk = (const float*)d_in[7];
    const float* Wv = (const float*)d_in[8];
    const float* bv = (const float*)d_in[9];
    const float* Wo = (const float*)d_in[10];
    const float* bo = (const float*)d_in[11];
    const float* proj = (const float*)d_in[12];
    const float* pos  = (const float*)d_in[13];
    float* out = (float*)d_out;

    void* fp = nullptr; cudaGetSymbolAddress(&fp, g_f);
    void* bp = nullptr; cudaGetSymbolAddress(&bp, g_b);
    float* F = (float*)fp;
    __nv_bfloat16* Bp = (__nv_bfloat16*)bp;

    static cudaStream_t s2 = nullptr;
    static cudaEvent_t evF, evW, evP, evVW, evK, evD;
    if (!s2) {
        cudaFuncSetAttribute(mma_nt, cudaFuncAttributeMaxDynamicSharedMemorySize, 81920);
        cudaFuncSetAttribute(mma_tn, cudaFuncAttributeMaxDynamicSharedMemorySize, 69632);
        cudaFuncSetAttribute(mma_nn, cudaFuncAttributeMaxDynamicSharedMemorySize, 75776);
        cudaStreamCreateWithFlags(&s2, cudaStreamNonBlocking);
        cudaEventCreateWithFlags(&evF,  cudaEventDisableTiming);
        cudaEventCreateWithFlags(&evW,  cudaEventDisableTiming);
        cudaEventCreateWithFlags(&evP,  cudaEventDisableTiming);
        cudaEventCreateWithFlags(&evVW, cudaEventDisableTiming);
        cudaEventCreateWithFlags(&evK,  cudaEventDisableTiming);
        cudaEventCreateWithFlags(&evD,  cudaEventDisableTiming);
    }
    const int SM_NT = 81920, SM_TN = 69632, SM_NN = 75776;
    dim3 tb(32, 8);

    // ---- main stream first node, then fork s2 off it ----
    clear_kernel<<<1, 32>>>();
    cudaEventRecord(evF, 0);

    // ---- stream 2: weights + value/proj conversions + W2 chain ----
    cudaStreamWaitEvent(s2, evF, 0);
    tconvW<<<dim3(8, 8, 2), tb, 0, s2>>>(Wq, Wk);
    cudaEventRecord(evW, s2);
    conv4<<<dim3(64, 1, 1), 256, 0, s2>>>(proj, proj, Bp + B_PRJH, SZW, SZW / 4);
    cudaEventRecord(evP, s2);
    conv4<<<dim3((unsigned)(SZB / 1024), 1, 1), 256, 0, s2>>>(value, value,
                                                              Bp + B_VINH, SZB, SZB / 4);
    conv4<<<dim3(64, 1, 2), 256, 0, s2>>>(Wv, Wo, Bp + B_WVINH, SZW, SZW / 4);
    // W2 = Wv @ Wo  (NN, tiny — overlapped)
    mma_nn<<<dim3(2, 2, 1), 256, SM_NN, s2>>>(
        Bp + B_WVINH, Bp + B_WVINL, Bp + B_WOINH, Bp + B_WOINL,
        nullptr, Bp + B_W2H, Bp + B_W2L,
        nullptr, nullptr, 0, 0, 0, 0, 0);
    bias2_kernel<<<1, 256, 0, s2>>>(bv, Wo, bo);
    // valueW2 = value @ W2 (big NN, fully overlapped)
    mma_nn<<<dim3(2, 64, 1), 256, SM_NN, s2>>>(
        Bp + B_VINH, Bp + B_VINL, Bp + B_W2H, Bp + B_W2L,
        nullptr, Bp + B_VW2H, Bp + B_VW2L,
        nullptr, nullptr, 0, 0, 0, 0, 0);
    cudaEventRecord(evVW, s2);

    // ---- main stream: q/k conversion only ----
    conv4<<<dim3((unsigned)(SZB / 1024), 1, 2), 256>>>(query, key, Bp + B_QINH, SZB, SZB / 4);

    // ---- main: q/k projections (needs WQT/WKT) ----
    cudaStreamWaitEvent(0, evW, 0);
    mma_nt<<<dim3(2, 64, 2), 256, SM_NT>>>(
        Bp + B_QINH, Bp + B_QINL, Bp + B_WQTH, Bp + B_WQTL,
        nullptr, Bp + B_QSH, Bp + B_QSL,
        bq, bk, pos,
        2 * SZB, 2 * SZW, 2 * SZB, 2, -1);

    // xq/xk: z=0 -> XQ, z=1 -> XK (+per-batch max); needs proj conv
    cudaStreamWaitEvent(0, evP, 0);
    mma_nt<<<dim3(2, 64, 2), 256, SM_NT>>>(
        Bp + B_QSH, Bp + B_QSL, Bp + B_PRJH, Bp + B_PRJL,
        F + F_XQ, nullptr, nullptr,
        nullptr, nullptr, nullptr,
        2 * SZB, 0, SZB, 0, 1);

    kp_kernel<<<NROWS, 256>>>();
    cudaEventRecord(evK, 0);

    // ---- stream 2: ksum + qpden (overlap with kvsW GEMM) ----
    cudaStreamWaitEvent(s2, evK, 0);
    ksump_kernel<<<dim3(KCH, BATCH), 256, 0, s2>>>();
    ksumfold_kernel<<<BATCH, 256, 0, s2>>>();
    qpden_kernel<<<NROWS, 256, 0, s2>>>();
    cudaEventRecord(evD, s2);

    // ---- main: kvsW = kp^T @ valueW2  (TN, split-K 16, 256 blocks) ----
    cudaStreamWaitEvent(0, evVW, 0);
    mma_tn<<<dim3(2, 2, 4 * TN_SPLIT), 256, SM_TN>>>(
        Bp + B_KPH, Bp + B_KPL, Bp + B_VW2H, Bp + B_VW2L,
        F + F_PART,
        (long)L_SEQ * MFEAT, (long)128 * MFEAT,
        (long)L_SEQ * 256,  (long)128 * 256,
        (long)TN_SPLIT * SZW, SZW);
    kvsured<<<dim3(256, BATCH), 256>>>();

    // ---- main: out = (qp @ kvsW)/den + (bvWo + bo)  (NN, batched) ----
    cudaStreamWaitEvent(0, evD, 0);
    mma_nn<<<dim3(2, 16, 4), 256, SM_NN>>>(
        Bp + B_QPH, Bp + B_QPL, Bp + B_KVSWH, Bp + B_KVSWL,
        out, nullptr, nullptr,
        F + F_BIAS2, F + F_DEN,
        (long)L_SEQ * 256, SZW, (long)L_SEQ * 256, L_SEQ, 5);
}